// round 12
// baseline (speedup 1.0000x reference)
#include <cuda_runtime.h>
#include <cuda_fp16.h>
#include <math.h>
#include <cstdint>

#define DT 0.001f
#define STEPS 128
#define UNITS 512
#define BATCH 64
#define MROWS (STEPS * BATCH)   // 8192
#define ACTION_DIM 256

// ---------------- scratch ----------------
__device__ __half g_states_h[MROWS * 1024];   // [x(512) | y(512)]
__device__ __half g_act1_h[MROWS * 2048];
__device__ __half g_act2_h[MROWS * 1024];
__device__ __half g_B0k[3 * 1024 * 512];      // [3][N=1024][K=512]
__device__ __half g_B1k[3 * 512 * 1024];      // [3][512][1024]
__device__ __half g_P2h[256 * 1024];          // [N=256][2K=1024]
// dependency counters (zeroed at end of every run by the last L2 CTA)
__device__ int c_hopf[8];                     // per 16-step block, target 64
__device__ int c_B0, c_B1, c_P2;              // targets 40 / 32 / 12
__device__ int c0[64], c1[64];                // targets 16 / 8
__device__ int c2;                            // L2 completion ticket (256)

__device__ __forceinline__ uint32_t smem_u32(const void* p) {
    uint32_t a;
    asm("{ .reg .u64 t; cvta.to.shared.u64 t, %1; cvt.u32.u64 %0, t; }" : "=r"(a) : "l"(p));
    return a;
}
__device__ __forceinline__ void cp16(uint32_t s, const void* g) {
    asm volatile("cp.async.cg.shared.global [%0], [%1], 16;" :: "r"(s), "l"(g));
}
__device__ __forceinline__ void ldm_x4(uint32_t* r, uint32_t addr) {
    asm volatile("ldmatrix.sync.aligned.m8n8.x4.shared.b16 {%0,%1,%2,%3}, [%4];"
                 : "=r"(r[0]), "=r"(r[1]), "=r"(r[2]), "=r"(r[3]) : "r"(addr));
}
__device__ __forceinline__ void mma_f16(float* c, const uint32_t* a, const uint32_t* b) {
    asm volatile(
        "mma.sync.aligned.m16n8k16.row.col.f32.f16.f16.f32 "
        "{%0,%1,%2,%3}, {%4,%5,%6,%7}, {%8,%9}, {%0,%1,%2,%3};"
        : "+f"(c[0]), "+f"(c[1]), "+f"(c[2]), "+f"(c[3])
        : "r"(a[0]), "r"(a[1]), "r"(a[2]), "r"(a[3]), "r"(b[0]), "r"(b[1]));
}
__device__ __forceinline__ uint32_t hadd2u(uint32_t a, uint32_t b) {
    __half2 r = __hadd2(*(__half2*)&a, *(__half2*)&b);
    return *(uint32_t*)&r;
}
// fast exact-enough tanh: 1 - 2/(exp2(2x*log2e)+1); saturates correctly at +/-inf
__device__ __forceinline__ float ftanh(float x) {
    float e;
    asm("ex2.approx.f32 %0, %1;" : "=f"(e) : "f"(x * 2.885390082f));
    float r;
    asm("rcp.approx.f32 %0, %1;" : "=f"(r) : "f"(e + 1.0f));
    return fmaf(-2.0f, r, 1.0f);
}
// cross-CTA dependency primitives
__device__ __forceinline__ void wait_cnt(int* p, int target) {
    if (threadIdx.x == 0) {
        int v;
        for (;;) {
            asm volatile("ld.acquire.gpu.global.s32 %0, [%1];" : "=r"(v) : "l"(p));
            if (v >= target) break;
            __nanosleep(128);
        }
    }
    __syncthreads();
}
__device__ __forceinline__ void sig_cnt(int* p) {
    __threadfence();
    __syncthreads();
    if (threadIdx.x == 0) atomicAdd(p, 1);
}

// ---------------- pack tile bodies (smem tiles live in dynamic smem) ----------------
__device__ __forceinline__ void pack_kar_tile(
    const float* __restrict__ Wr, const float* __restrict__ Wi,
    __half* __restrict__ Bk, int K, int N, int k0, int n0,
    float (*tr)[33], float (*ti)[33], int tx, int ty0) {
#pragma unroll
    for (int i = 0; i < 4; i++) {
        int ty = ty0 + i * 8;
        tr[ty][tx] = Wr[(size_t)(k0 + ty) * N + n0 + tx];
        ti[ty][tx] = Wi[(size_t)(k0 + ty) * N + n0 + tx];
    }
    __syncthreads();
    const size_t NK = (size_t)N * K;
#pragma unroll
    for (int i = 0; i < 4; i++) {
        int ty = ty0 + i * 8;
        float wr = tr[tx][ty], wi = ti[tx][ty];
        size_t o = (size_t)(n0 + ty) * K + k0 + tx;
        Bk[o] = __float2half_rn(wr);
        Bk[NK + o] = __float2half_rn(wi - wr);
        Bk[2 * NK + o] = __float2half_rn(wr + wi);
    }
    __syncthreads();
}
__device__ __forceinline__ void pack_half_tile(
    const float* __restrict__ Wr, const float* __restrict__ Wi,
    __half* __restrict__ PT, int K, int N, int k0, int n0,
    float (*tile)[33], int tx, int ty0) {
#pragma unroll
    for (int i = 0; i < 4; i++) {
        int ty = ty0 + i * 8;
        int k = k0 + ty;
        float v = (k < K) ? Wr[(size_t)k * N + n0 + tx] : -Wi[(size_t)(k - K) * N + n0 + tx];
        tile[ty][tx] = v;
    }
    __syncthreads();
#pragma unroll
    for (int i = 0; i < 4; i++) {
        int ty = ty0 + i * 8;
        PT[(size_t)(n0 + ty) * (2 * K) + k0 + tx] = __float2half_rn(tile[tx][ty]);
    }
    __syncthreads();
}

// ---------------- hopf body with per-16-step signaling ----------------
__device__ __forceinline__ void hopf_body(
    const float* __restrict__ z0, const float* __restrict__ omega,
    const float* __restrict__ bpar, __half* __restrict__ states,
    float* __restrict__ out_z1) {
    int tid = blockIdx.x * 256 + threadIdx.x;      // 0..16383
    int bi = tid >> 8;
    int i0 = tid & 255;
    int i1 = i0 + 256;
    const float om = omega[bi];
    float x0 = z0[bi * 1024 + i0],          y0 = z0[bi * 1024 + UNITS + i0];
    float x1 = z0[bi * 1024 + i1],          y1 = z0[bi * 1024 + UNITS + i1];
    const float w0 = om * (float)(i0 + 1),  w1 = om * (float)(i1 + 1);
    const float b0 = bpar[bi * UNITS + i0], b1 = bpar[bi * UNITS + i1];
    for (int tb = 0; tb < 8; tb++) {
#pragma unroll 4
        for (int tt = 0; tt < 16; tt++) {
            int t = tb * 16 + tt;
            float r20 = x0 * x0 + y0 * y0;
            float r21 = x1 * x1 + y1 * y1;
            float g0 = b0 - r20, g1 = b1 - r21;
            float dx0 = g0 * x0 - w0 * y0, dy0 = g0 * y0 + w0 * x0;
            float dx1 = g1 * x1 - w1 * y1, dy1 = g1 * y1 + w1 * x1;
            x0 += DT * dx0; y0 += DT * dy0;
            x1 += DT * dx1; y1 += DT * dy1;
            __half* row = states + ((size_t)(t * BATCH + bi)) * 1024;
            row[i0] = __float2half_rn(x0);
            row[i1] = __float2half_rn(x1);
            row[UNITS + i0] = __float2half_rn(y0);
            row[UNITS + i1] = __float2half_rn(y1);
            if (t == 0) {
                out_z1[bi * 1024 + i0] = x0;
                out_z1[bi * 1024 + i1] = x1;
                out_z1[bi * 1024 + UNITS + i0] = y0;
                out_z1[bi * 1024 + UNITS + i1] = y1;
            }
        }
        sig_cnt(&c_hopf[tb]);
    }
}

// ---------------- GEMM bodies ----------------
#define KAR_BUF 114688   // per-buffer smem: Ax 32K + Ay 32K + B 48K
#define L2C_A  (64 * 128)
#define L2C    (L2C_A + 128 * 128)

__device__ __forceinline__ void kar_body(
    char* sm, const __half* __restrict__ Act, const __half* __restrict__ Bk,
    const float* __restrict__ br, const float* __restrict__ bi,
    __half* __restrict__ Out, int K, int N, int bnb, int bmb) {
    const uint32_t smb = smem_u32(sm);
    const int tid = threadIdx.x;
    const int wid = tid >> 5, lane = tid & 31;
    const int wm = wid >> 1, wn = wid & 1;
    const int g = lane >> 2, tq = lane & 3;
    const int lm = lane & 15, l16 = lane >> 4, fx = lane & 7;

    const int bm = bmb * 128;
    const int bn = bnb * 64;
    const int nch = K / 128;
    const int K2 = 2 * K;
    const size_t NK = (size_t)N * K;

    const int crow = tid >> 3;
    const int cslot = tid & 7;
    const uint32_t swz16 = (uint32_t)((cslot ^ (crow & 7)) << 4);

    float acc1[2][4][4], acc2[2][4][4], acc3[2][4][4];
#pragma unroll
    for (int mt = 0; mt < 2; mt++)
#pragma unroll
        for (int nt = 0; nt < 4; nt++)
#pragma unroll
            for (int r = 0; r < 4; r++) {
                acc1[mt][nt][r] = 0.0f; acc2[mt][nt][r] = 0.0f; acc3[mt][nt][r] = 0.0f;
            }

    auto issue = [&](int c) {
        const uint32_t base = smb + (uint32_t)(c & 1) * KAR_BUF;
#pragma unroll
        for (int op = 0; op < 2; op++)
#pragma unroll
            for (int pan = 0; pan < 2; pan++)
#pragma unroll
                for (int it = 0; it < 4; it++) {
                    int row = crow + it * 32;
                    uint32_t s = base + op * 32768 + pan * 16384 + (uint32_t)row * 128 + swz16;
                    const __half* gp = Act + (size_t)(bm + row) * K2 + op * K +
                                       c * 128 + pan * 64 + cslot * 8;
                    cp16(s, gp);
                }
#pragma unroll
        for (int mat = 0; mat < 3; mat++)
#pragma unroll
            for (int pan = 0; pan < 2; pan++)
#pragma unroll
                for (int it = 0; it < 2; it++) {
                    int row = crow + it * 32;
                    uint32_t s = base + 65536 + mat * 16384 + pan * 8192 +
                                 (uint32_t)row * 128 + swz16;
                    const __half* gp = Bk + (size_t)mat * NK + (size_t)(bn + row) * K +
                                       c * 128 + pan * 64 + cslot * 8;
                    cp16(s, gp);
                }
        asm volatile("cp.async.commit_group;" ::: "memory");
    };

    issue(0);

    const uint32_t a_row = (uint32_t)(wm * 32 + lm) * 128;
    const uint32_t b_row = (uint32_t)(wn * 32 + lm) * 128;

    for (int c = 0; c < nch; c++) {
        asm volatile("cp.async.wait_group 0;" ::: "memory");
        __syncthreads();
        if (c + 1 < nch) issue(c + 1);
        const uint32_t cb = smb + (uint32_t)(c & 1) * KAR_BUF;

#pragma unroll
        for (int kk = 0; kk < 8; kk++) {
            const int pan = kk >> 2, ks = kk & 3;
            const uint32_t kslot = (uint32_t)(((ks * 2 + l16) ^ fx) << 4);
            uint32_t af[2][2][4];
            const uint32_t ab = cb + pan * 16384 + a_row + kslot;
            ldm_x4(af[0][0], ab);
            ldm_x4(af[0][1], ab + 16 * 128);
            ldm_x4(af[1][0], ab + 32768);
            ldm_x4(af[1][1], ab + 32768 + 16 * 128);
            uint32_t bf[3][4][2];
            const uint32_t bb = cb + 65536 + pan * 8192 + b_row + kslot;
#pragma unroll
            for (int mat = 0; mat < 3; mat++) {
                uint32_t r[4];
                ldm_x4(r, bb + mat * 16384);
                bf[mat][0][0] = r[0]; bf[mat][1][0] = r[1];
                bf[mat][0][1] = r[2]; bf[mat][1][1] = r[3];
                ldm_x4(r, bb + mat * 16384 + 16 * 128);
                bf[mat][2][0] = r[0]; bf[mat][3][0] = r[1];
                bf[mat][2][1] = r[2]; bf[mat][3][1] = r[3];
            }
            uint32_t as[2][4];
#pragma unroll
            for (int mt = 0; mt < 2; mt++)
#pragma unroll
                for (int i = 0; i < 4; i++)
                    as[mt][i] = hadd2u(af[0][mt][i], af[1][mt][i]);
#pragma unroll
            for (int mt = 0; mt < 2; mt++)
#pragma unroll
                for (int nt = 0; nt < 4; nt++) {
                    mma_f16(acc1[mt][nt], as[mt],    bf[0][nt]);
                    mma_f16(acc2[mt][nt], af[0][mt], bf[1][nt]);
                    mma_f16(acc3[mt][nt], af[1][mt], bf[2][nt]);
                }
        }
    }

#pragma unroll
    for (int mt = 0; mt < 2; mt++) {
        const int row0 = bm + wm * 32 + mt * 16 + g;
#pragma unroll
        for (int nt = 0; nt < 4; nt++) {
            const int col = bn + wn * 32 + nt * 8 + 2 * tq;
            const float br0 = br[col], br1 = br[col + 1];
            const float bi0 = bi[col], bi1 = bi[col + 1];
            const float* a1 = acc1[mt][nt];
            const float* a2 = acc2[mt][nt];
            const float* a3 = acc3[mt][nt];
            const float x0 = ftanh(a1[0] - a3[0] + br0);
            const float x1 = ftanh(a1[1] - a3[1] + br1);
            const float x2 = ftanh(a1[2] - a3[2] + br0);
            const float x3 = ftanh(a1[3] - a3[3] + br1);
            const float y0 = ftanh(a1[0] + a2[0] + bi0);
            const float y1 = ftanh(a1[1] + a2[1] + bi1);
            const float y2 = ftanh(a1[2] + a2[2] + bi0);
            const float y3 = ftanh(a1[3] + a2[3] + bi1);
            __half* o0 = Out + (size_t)row0 * (2 * N) + col;
            __half* o1 = Out + (size_t)(row0 + 8) * (2 * N) + col;
            *(__half2*)o0 = __floats2half2_rn(x0, x1);
            *(__half2*)o1 = __floats2half2_rn(x2, x3);
            *(__half2*)(o0 + N) = __floats2half2_rn(y0, y1);
            *(__half2*)(o1 + N) = __floats2half2_rn(y2, y3);
        }
    }
}

__device__ __forceinline__ void l2_body(
    char* sm, const __half* __restrict__ A, const __half* __restrict__ Bw,
    const float* __restrict__ bias, float* __restrict__ C, int K, int bnb, int bmb) {
    const uint32_t smb = smem_u32(sm);
    const int tid = threadIdx.x;
    const int wid = tid >> 5, lane = tid & 31;
    const int wm = wid >> 2, wn = wid & 3;
    const int g = lane >> 2, tq = lane & 3;
    const int lm = lane & 15, l16 = lane >> 4, fx = lane & 7;

    const int bm = bmb * 64;
    const int bn = bnb * 128;
    const int nch = K / 64;

    const int crow = tid >> 3;
    const int cslot = tid & 7;
    const uint32_t swz16 = (uint32_t)((cslot ^ (crow & 7)) << 4);
    const __half* Agb = A  + (size_t)(bm + crow) * K + cslot * 8;
    const __half* Bgb = Bw + (size_t)(bn + crow) * K + cslot * 8;

    float acc[2][4][4];
#pragma unroll
    for (int mt = 0; mt < 2; mt++)
#pragma unroll
        for (int nt = 0; nt < 4; nt++)
#pragma unroll
            for (int r = 0; r < 4; r++) acc[mt][nt][r] = 0.0f;

    auto issue = [&](int c) {
        const uint32_t base = smb + (uint32_t)(c & 1) * L2C;
#pragma unroll
        for (int it = 0; it < 2; it++)
            cp16(base + (uint32_t)(crow + it * 32) * 128 + swz16,
                 Agb + (size_t)it * 32 * K + c * 64);
#pragma unroll
        for (int it = 0; it < 4; it++)
            cp16(base + L2C_A + (uint32_t)(crow + it * 32) * 128 + swz16,
                 Bgb + (size_t)it * 32 * K + c * 64);
        asm volatile("cp.async.commit_group;" ::: "memory");
    };

    issue(0);

    const uint32_t a_row = (uint32_t)(wm * 32 + lm) * 128;
    const uint32_t b_row = (uint32_t)(wn * 32 + lm) * 128;

    for (int c = 0; c < nch; c++) {
        asm volatile("cp.async.wait_group 0;" ::: "memory");
        __syncthreads();
        if (c + 1 < nch) issue(c + 1);
        const uint32_t cb = smb + (uint32_t)(c & 1) * L2C;

#pragma unroll
        for (int kk = 0; kk < 4; kk++) {
            const uint32_t kslot = (uint32_t)(((kk * 2 + l16) ^ fx) << 4);
            uint32_t af[2][4];
            ldm_x4(af[0], cb + a_row + kslot);
            ldm_x4(af[1], cb + a_row + 16 * 128 + kslot);
            uint32_t bf[4][2];
#pragma unroll
            for (int p = 0; p < 2; p++) {
                uint32_t r[4];
                ldm_x4(r, cb + L2C_A + b_row + (uint32_t)(p * 16) * 128 + kslot);
                bf[2 * p][0] = r[0]; bf[2 * p + 1][0] = r[1];
                bf[2 * p][1] = r[2]; bf[2 * p + 1][1] = r[3];
            }
#pragma unroll
            for (int mt = 0; mt < 2; mt++)
#pragma unroll
                for (int nt = 0; nt < 4; nt++)
                    mma_f16(acc[mt][nt], af[mt], bf[nt]);
        }
    }

#pragma unroll
    for (int mt = 0; mt < 2; mt++) {
        const int row0 = bm + wm * 32 + mt * 16 + g;
#pragma unroll
        for (int nt = 0; nt < 4; nt++) {
            const int col = bn + wn * 32 + nt * 8 + 2 * tq;
            const float bv0 = bias[col], bv1 = bias[col + 1];
            const float v0 = ftanh(acc[mt][nt][0] + bv0);
            const float v1 = ftanh(acc[mt][nt][1] + bv1);
            const float v2 = ftanh(acc[mt][nt][2] + bv0);
            const float v3 = ftanh(acc[mt][nt][3] + bv1);
            const int t0 = row0 >> 6, b0 = row0 & 63;
            const int r1 = row0 + 8;
            const int t1 = r1 >> 6, b1 = r1 & 63;
            *(float2*)(C + (size_t)b0 * (STEPS * ACTION_DIM) + t0 * ACTION_DIM + col) =
                make_float2(v0, v1);
            *(float2*)(C + (size_t)b1 * (STEPS * ACTION_DIM) + t1 * ACTION_DIM + col) =
                make_float2(v2, v3);
        }
    }
}

// ---------------- the mega kernel ----------------
// blocks [0,64):      hopf (signals c_hopf[tb] per 16 steps)
// blocks [64,148):    pack workers: 40 B0 / 32 B1 / 12 P2 (grid-strided tiles)
// blocks [148,1172):  L0 tiles   wait c_B0, c_hopf[(2bm+1)/16]; signal c0[bm]
// blocks [1172,1684): L1 tiles   wait c_B1, c0[bm]==16;         signal c1[bm]
// blocks [1684,1940): L2 tiles   wait c_P2, c1[bm64/2]==8;      ticket-reset counters
__global__ __launch_bounds__(256, 1)
void mlp_mega(const float* __restrict__ z, const float* __restrict__ omega,
              const float* __restrict__ bpar,
              const float* __restrict__ W0r, const float* __restrict__ W0i,
              const float* __restrict__ b0r, const float* __restrict__ b0i,
              const float* __restrict__ W1r, const float* __restrict__ W1i,
              const float* __restrict__ b1r, const float* __restrict__ b1i,
              const float* __restrict__ W2r, const float* __restrict__ W2i,
              const float* __restrict__ b2r,
              __half* __restrict__ st, __half* __restrict__ a1,
              __half* __restrict__ a2,
              __half* __restrict__ B0, __half* __restrict__ B1,
              __half* __restrict__ P2,
              float* __restrict__ out, float* __restrict__ out_z1) {
    extern __shared__ char sm[];
    const int b = blockIdx.x;
    const int tid = threadIdx.x;

    if (b < 64) {
        hopf_body(z, omega, bpar, st, out_z1);
    } else if (b < 148) {
        float (*t1)[33] = (float (*)[33])sm;
        float (*t2)[33] = (float (*)[33])(sm + 4352);
        const int tx = tid & 31, ty0 = tid >> 5;
        const int pid = b - 64;
        if (pid < 40) {
            for (int tt = pid; tt < 512; tt += 40)
                pack_kar_tile(W0r, W0i, B0, 512, 1024,
                              (tt & 15) * 32, (tt >> 4) * 32, t1, t2, tx, ty0);
            sig_cnt(&c_B0);
        } else if (pid < 72) {
            for (int tt = pid - 40; tt < 512; tt += 32)
                pack_kar_tile(W1r, W1i, B1, 1024, 512,
                              (tt & 31) * 32, (tt >> 5) * 32, t1, t2, tx, ty0);
            sig_cnt(&c_B1);
        } else {
            for (int tt = pid - 72; tt < 256; tt += 12)
                pack_half_tile(W2r, W2i, P2, 512, 256,
                               (tt & 31) * 32, (tt >> 5) * 32, t1, tx, ty0);
            sig_cnt(&c_P2);
        }
    } else if (b < 1172) {
        const int i = b - 148;
        const int bn = i & 15, bm = i >> 4;
        wait_cnt(&c_B0, 40);
        wait_cnt(&c_hopf[(2 * bm + 1) >> 4], 64);
        kar_body(sm, st, B0, b0r, b0i, a1, 512, 1024, bn, bm);
        sig_cnt(&c0[bm]);
    } else if (b < 1684) {
        const int i = b - 1172;
        const int bn = i & 7, bm = i >> 3;
        wait_cnt(&c_B1, 32);
        wait_cnt(&c0[bm], 16);
        kar_body(sm, a1, B1, b1r, b1i, a2, 1024, 512, bn, bm);
        sig_cnt(&c1[bm]);
    } else {
        const int i = b - 1684;
        const int bn = i & 1, bm64 = i >> 1;
        wait_cnt(&c_P2, 12);
        wait_cnt(&c1[bm64 >> 1], 8);
        l2_body(sm, a2, P2, b2r, out, 1024, bn, bm64);
        // ticket-based counter reset: last L2 CTA restores all counters to 0
        if (tid == 0) {
            if (atomicAdd(&c2, 1) == 255) {
#pragma unroll
                for (int j = 0; j < 8; j++) c_hopf[j] = 0;
                c_B0 = 0; c_B1 = 0; c_P2 = 0;
                for (int j = 0; j < 64; j++) { c0[j] = 0; c1[j] = 0; }
                c2 = 0;
            }
        }
    }
}

// ---------------- launch ----------------
extern "C" void kernel_launch(void* const* d_in, const int* in_sizes, int n_in,
                              void* d_out, int out_size) {
    const float* z     = (const float*)d_in[0];
    const float* omega = (const float*)d_in[1];
    const float* bpar  = (const float*)d_in[2];
    const float* W0r = (const float*)d_in[3];
    const float* W0i = (const float*)d_in[4];
    const float* b0r = (const float*)d_in[5];
    const float* b0i = (const float*)d_in[6];
    const float* W1r = (const float*)d_in[7];
    const float* W1i = (const float*)d_in[8];
    const float* b1r = (const float*)d_in[9];
    const float* b1i = (const float*)d_in[10];
    const float* W2r = (const float*)d_in[11];
    const float* W2i = (const float*)d_in[12];
    const float* b2r = (const float*)d_in[13];

    float* out = (float*)d_out;                                 // (64, 128, 256)
    float* out_z1 = out + (size_t)BATCH * STEPS * ACTION_DIM;   // (64, 1024)

    __half *B0, *B1, *P2, *st, *a1, *a2;
    cudaGetSymbolAddress((void**)&B0, g_B0k);
    cudaGetSymbolAddress((void**)&B1, g_B1k);
    cudaGetSymbolAddress((void**)&P2, g_P2h);
    cudaGetSymbolAddress((void**)&st, g_states_h);
    cudaGetSymbolAddress((void**)&a1, g_act1_h);
    cudaGetSymbolAddress((void**)&a2, g_act2_h);

    constexpr int SM_MEGA = 2 * KAR_BUF;     // 229376
    cudaFuncSetAttribute(mlp_mega, cudaFuncAttributeMaxDynamicSharedMemorySize, SM_MEGA);

    mlp_mega<<<1940, 256, SM_MEGA>>>(z, omega, bpar,
                                     W0r, W0i, b0r, b0i,
                                     W1r, W1i, b1r, b1i,
                                     W2r, W2i, b2r,
                                     st, a1, a2, B0, B1, P2,
                                     out, out_z1);
}

// round 13
// speedup vs baseline: 1.0129x; 1.0129x over previous
#include <cuda_runtime.h>
#include <cuda_fp16.h>
#include <math.h>
#include <cstdint>

#define DT 0.001f
#define STEPS 128
#define UNITS 512
#define BATCH 64
#define MROWS (STEPS * BATCH)   // 8192
#define ACTION_DIM 256

// ---------------- scratch ----------------
__device__ __half g_states_h[MROWS * 1024];   // [x(512) | y(512)]
__device__ __half g_act1_h[MROWS * 2048];     // [x(1024) | y(1024)]
__device__ __half g_act2_h[MROWS * 1024];     // [x(512) | y(512)]
__device__ __half g_B0k[3 * 1024 * 512];      // layer0 karatsuba B: [3][N=1024][K=512]
__device__ __half g_B1k[3 * 512 * 1024];      // layer1: [3][512][1024]
__device__ __half g_P2h[256 * 1024];          // layer2: [N=256][2K=1024]
__device__ int g_c0[64];                      // a1 row-block (128 rows) counters, target 16
__device__ int g_c1[64];                      // a2 row-block counters, target 8

__device__ __forceinline__ uint32_t smem_u32(const void* p) {
    uint32_t a;
    asm("{ .reg .u64 t; cvta.to.shared.u64 t, %1; cvt.u32.u64 %0, t; }" : "=r"(a) : "l"(p));
    return a;
}
__device__ __forceinline__ void cp16(uint32_t s, const void* g) {
    asm volatile("cp.async.cg.shared.global [%0], [%1], 16;" :: "r"(s), "l"(g));
}
__device__ __forceinline__ void ldm_x4(uint32_t* r, uint32_t addr) {
    asm volatile("ldmatrix.sync.aligned.m8n8.x4.shared.b16 {%0,%1,%2,%3}, [%4];"
                 : "=r"(r[0]), "=r"(r[1]), "=r"(r[2]), "=r"(r[3]) : "r"(addr));
}
__device__ __forceinline__ void mma_f16(float* c, const uint32_t* a, const uint32_t* b) {
    asm volatile(
        "mma.sync.aligned.m16n8k16.row.col.f32.f16.f16.f32 "
        "{%0,%1,%2,%3}, {%4,%5,%6,%7}, {%8,%9}, {%0,%1,%2,%3};"
        : "+f"(c[0]), "+f"(c[1]), "+f"(c[2]), "+f"(c[3])
        : "r"(a[0]), "r"(a[1]), "r"(a[2]), "r"(a[3]), "r"(b[0]), "r"(b[1]));
}
__device__ __forceinline__ uint32_t hadd2u(uint32_t a, uint32_t b) {
    __half2 r = __hadd2(*(__half2*)&a, *(__half2*)&b);
    return *(uint32_t*)&r;
}
// fast tanh: 1 - 2/(exp2(2x*log2e)+1); abs err ~1e-6, saturates correctly
__device__ __forceinline__ float ftanh(float x) {
    float e;
    asm("ex2.approx.f32 %0, %1;" : "=f"(e) : "f"(x * 2.885390082f));
    float r;
    asm("rcp.approx.f32 %0, %1;" : "=f"(r) : "f"(e + 1.0f));
    return fmaf(-2.0f, r, 1.0f);
}
// cross-CTA dependency primitives
__device__ __forceinline__ void wait_cnt(int* p, int target) {
    if (threadIdx.x == 0) {
        int v;
        for (;;) {
            asm volatile("ld.acquire.gpu.global.s32 %0, [%1];" : "=r"(v) : "l"(p));
            if (v >= target) break;
            __nanosleep(128);
        }
    }
    __syncthreads();
}
__device__ __forceinline__ void sig_cnt(int* p) {
    __threadfence();
    __syncthreads();
    if (threadIdx.x == 0) atomicAdd(p, 1);
}

// ---------------- merged prep: weight packing + hopf + counter reset ----------------
__device__ __forceinline__ void pack_kar_body(
    const float* __restrict__ Wr, const float* __restrict__ Wi,
    __half* __restrict__ Bk, int K, int N,
    float (*tr)[33], float (*ti)[33]) {
    int k0 = blockIdx.x * 32;
    int n0 = blockIdx.y * 32;
    if (k0 >= K || n0 >= N) return;
    int tx = threadIdx.x, ty0 = threadIdx.y;
#pragma unroll
    for (int i = 0; i < 4; i++) {
        int ty = ty0 + i * 8;
        tr[ty][tx] = Wr[(size_t)(k0 + ty) * N + n0 + tx];
        ti[ty][tx] = Wi[(size_t)(k0 + ty) * N + n0 + tx];
    }
    __syncthreads();
    const size_t NK = (size_t)N * K;
#pragma unroll
    for (int i = 0; i < 4; i++) {
        int ty = ty0 + i * 8;
        float wr = tr[tx][ty], wi = ti[tx][ty];
        size_t o = (size_t)(n0 + ty) * K + k0 + tx;
        Bk[o] = __float2half_rn(wr);
        Bk[NK + o] = __float2half_rn(wi - wr);
        Bk[2 * NK + o] = __float2half_rn(wr + wi);
    }
}
__device__ __forceinline__ void pack_half_body(
    const float* __restrict__ Wr, const float* __restrict__ Wi,
    __half* __restrict__ PT, int K, int N, float (*tile)[33]) {
    int k0 = blockIdx.x * 32;
    int n0 = blockIdx.y * 32;
    if (k0 >= 2 * K || n0 >= N) return;
    int tx = threadIdx.x, ty0 = threadIdx.y;
#pragma unroll
    for (int i = 0; i < 4; i++) {
        int ty = ty0 + i * 8;
        int k = k0 + ty;
        float v = (k < K) ? Wr[(size_t)k * N + n0 + tx] : -Wi[(size_t)(k - K) * N + n0 + tx];
        tile[ty][tx] = v;
    }
    __syncthreads();
#pragma unroll
    for (int i = 0; i < 4; i++) {
        int ty = ty0 + i * 8;
        PT[(size_t)(n0 + ty) * (2 * K) + k0 + tx] = __float2half_rn(tile[tx][ty]);
    }
}
__device__ __forceinline__ void hopf_body(
    const float* __restrict__ z0, const float* __restrict__ omega,
    const float* __restrict__ bpar, __half* __restrict__ states,
    float* __restrict__ out_z1) {
    if (blockIdx.y >= 2) return;
    int blk = blockIdx.y * 32 + blockIdx.x;
    int tin = threadIdx.y * 32 + threadIdx.x;
    int tid = blk * 256 + tin;
    int bi = tid >> 8;
    int i0 = tid & 255;
    int i1 = i0 + 256;
    const float om = omega[bi];
    float x0 = z0[bi * 1024 + i0],          y0 = z0[bi * 1024 + UNITS + i0];
    float x1 = z0[bi * 1024 + i1],          y1 = z0[bi * 1024 + UNITS + i1];
    const float w0 = om * (float)(i0 + 1),  w1 = om * (float)(i1 + 1);
    const float b0 = bpar[bi * UNITS + i0], b1 = bpar[bi * UNITS + i1];
#pragma unroll 4
    for (int t = 0; t < STEPS; t++) {
        float r20 = x0 * x0 + y0 * y0;
        float r21 = x1 * x1 + y1 * y1;
        float g0 = b0 - r20, g1 = b1 - r21;
        float dx0 = g0 * x0 - w0 * y0, dy0 = g0 * y0 + w0 * x0;
        float dx1 = g1 * x1 - w1 * y1, dy1 = g1 * y1 + w1 * x1;
        x0 += DT * dx0; y0 += DT * dy0;
        x1 += DT * dx1; y1 += DT * dy1;
        __half* row = states + ((size_t)(t * BATCH + bi)) * 1024;
        row[i0] = __float2half_rn(x0);
        row[i1] = __float2half_rn(x1);
        row[UNITS + i0] = __float2half_rn(y0);
        row[UNITS + i1] = __float2half_rn(y1);
        if (t == 0) {
            out_z1[bi * 1024 + i0] = x0;
            out_z1[bi * 1024 + i1] = x1;
            out_z1[bi * 1024 + UNITS + i0] = y0;
            out_z1[bi * 1024 + UNITS + i1] = y1;
        }
    }
}
__global__ void prep_all(const float* z, const float* omega, const float* bpar,
                         const float* W0r, const float* W0i,
                         const float* W1r, const float* W1i,
                         const float* W2r, const float* W2i,
                         __half* B0, __half* B1, __half* P2,
                         __half* states, float* out_z1) {
    __shared__ float t1[32][33], t2[32][33];
    int zz = blockIdx.z;
    if (zz == 0)      pack_kar_body(W0r, W0i, B0, 512, 1024, t1, t2);
    else if (zz == 1) pack_kar_body(W1r, W1i, B1, 1024, 512, t1, t2);
    else if (zz == 2) {
        pack_half_body(W2r, W2i, P2, 512, 256, t1);
        if (blockIdx.x == 0 && blockIdx.y == 0) {
            int t = threadIdx.y * 32 + threadIdx.x;
            if (t < 64) { g_c0[t] = 0; g_c1[t] = 0; }
        }
    } else hopf_body(z, omega, bpar, states, out_z1);
}

// ---------------- fused GEMM pipeline bodies ----------------
#define KAR_BUF 114688   // per-buffer smem: Ax 32K + Ay 32K + B 48K
#define L2C_A  (64 * 128)
#define L2C    (L2C_A + 128 * 128)

__device__ __forceinline__ void kar_body(
    char* sm, const __half* __restrict__ Act, const __half* __restrict__ Bk,
    const float* __restrict__ br, const float* __restrict__ bi,
    __half* __restrict__ Out, int K, int N, int bnb, int bmb) {
    const uint32_t smb = smem_u32(sm);
    const int tid = threadIdx.x;
    const int wid = tid >> 5, lane = tid & 31;
    const int wm = wid >> 1, wn = wid & 1;
    const int g = lane >> 2, tq = lane & 3;
    const int lm = lane & 15, l16 = lane >> 4, fx = lane & 7;

    const int bm = bmb * 128;
    const int bn = bnb * 64;
    const int nch = K / 128;
    const int K2 = 2 * K;
    const size_t NK = (size_t)N * K;

    const int crow = tid >> 3;
    const int cslot = tid & 7;
    const uint32_t swz16 = (uint32_t)((cslot ^ (crow & 7)) << 4);

    float acc1[2][4][4], acc2[2][4][4], acc3[2][4][4];
#pragma unroll
    for (int mt = 0; mt < 2; mt++)
#pragma unroll
        for (int nt = 0; nt < 4; nt++)
#pragma unroll
            for (int r = 0; r < 4; r++) {
                acc1[mt][nt][r] = 0.0f; acc2[mt][nt][r] = 0.0f; acc3[mt][nt][r] = 0.0f;
            }

    auto issue = [&](int c) {
        const uint32_t base = smb + (uint32_t)(c & 1) * KAR_BUF;
#pragma unroll
        for (int op = 0; op < 2; op++)
#pragma unroll
            for (int pan = 0; pan < 2; pan++)
#pragma unroll
                for (int it = 0; it < 4; it++) {
                    int row = crow + it * 32;
                    uint32_t s = base + op * 32768 + pan * 16384 + (uint32_t)row * 128 + swz16;
                    const __half* gp = Act + (size_t)(bm + row) * K2 + op * K +
                                       c * 128 + pan * 64 + cslot * 8;
                    cp16(s, gp);
                }
#pragma unroll
        for (int mat = 0; mat < 3; mat++)
#pragma unroll
            for (int pan = 0; pan < 2; pan++)
#pragma unroll
                for (int it = 0; it < 2; it++) {
                    int row = crow + it * 32;
                    uint32_t s = base + 65536 + mat * 16384 + pan * 8192 +
                                 (uint32_t)row * 128 + swz16;
                    const __half* gp = Bk + (size_t)mat * NK + (size_t)(bn + row) * K +
                                       c * 128 + pan * 64 + cslot * 8;
                    cp16(s, gp);
                }
        asm volatile("cp.async.commit_group;" ::: "memory");
    };

    issue(0);

    const uint32_t a_row = (uint32_t)(wm * 32 + lm) * 128;
    const uint32_t b_row = (uint32_t)(wn * 32 + lm) * 128;

    for (int c = 0; c < nch; c++) {
        asm volatile("cp.async.wait_group 0;" ::: "memory");
        __syncthreads();
        if (c + 1 < nch) issue(c + 1);
        const uint32_t cb = smb + (uint32_t)(c & 1) * KAR_BUF;

#pragma unroll
        for (int kk = 0; kk < 8; kk++) {
            const int pan = kk >> 2, ks = kk & 3;
            const uint32_t kslot = (uint32_t)(((ks * 2 + l16) ^ fx) << 4);
            uint32_t af[2][2][4];
            const uint32_t ab = cb + pan * 16384 + a_row + kslot;
            ldm_x4(af[0][0], ab);
            ldm_x4(af[0][1], ab + 16 * 128);
            ldm_x4(af[1][0], ab + 32768);
            ldm_x4(af[1][1], ab + 32768 + 16 * 128);
            uint32_t bf[3][4][2];
            const uint32_t bb = cb + 65536 + pan * 8192 + b_row + kslot;
#pragma unroll
            for (int mat = 0; mat < 3; mat++) {
                uint32_t r[4];
                ldm_x4(r, bb + mat * 16384);
                bf[mat][0][0] = r[0]; bf[mat][1][0] = r[1];
                bf[mat][0][1] = r[2]; bf[mat][1][1] = r[3];
                ldm_x4(r, bb + mat * 16384 + 16 * 128);
                bf[mat][2][0] = r[0]; bf[mat][3][0] = r[1];
                bf[mat][2][1] = r[2]; bf[mat][3][1] = r[3];
            }
            uint32_t as[2][4];
#pragma unroll
            for (int mt = 0; mt < 2; mt++)
#pragma unroll
                for (int i = 0; i < 4; i++)
                    as[mt][i] = hadd2u(af[0][mt][i], af[1][mt][i]);
#pragma unroll
            for (int mt = 0; mt < 2; mt++)
#pragma unroll
                for (int nt = 0; nt < 4; nt++) {
                    mma_f16(acc1[mt][nt], as[mt],    bf[0][nt]);
                    mma_f16(acc2[mt][nt], af[0][mt], bf[1][nt]);
                    mma_f16(acc3[mt][nt], af[1][mt], bf[2][nt]);
                }
        }
    }

#pragma unroll
    for (int mt = 0; mt < 2; mt++) {
        const int row0 = bm + wm * 32 + mt * 16 + g;
#pragma unroll
        for (int nt = 0; nt < 4; nt++) {
            const int col = bn + wn * 32 + nt * 8 + 2 * tq;
            const float br0 = br[col], br1 = br[col + 1];
            const float bi0 = bi[col], bi1 = bi[col + 1];
            const float* a1 = acc1[mt][nt];
            const float* a2 = acc2[mt][nt];
            const float* a3 = acc3[mt][nt];
            const float x0 = ftanh(a1[0] - a3[0] + br0);
            const float x1 = ftanh(a1[1] - a3[1] + br1);
            const float x2 = ftanh(a1[2] - a3[2] + br0);
            const float x3 = ftanh(a1[3] - a3[3] + br1);
            const float y0 = ftanh(a1[0] + a2[0] + bi0);
            const float y1 = ftanh(a1[1] + a2[1] + bi1);
            const float y2 = ftanh(a1[2] + a2[2] + bi0);
            const float y3 = ftanh(a1[3] + a2[3] + bi1);
            __half* o0 = Out + (size_t)row0 * (2 * N) + col;
            __half* o1 = Out + (size_t)(row0 + 8) * (2 * N) + col;
            *(__half2*)o0 = __floats2half2_rn(x0, x1);
            *(__half2*)o1 = __floats2half2_rn(x2, x3);
            *(__half2*)(o0 + N) = __floats2half2_rn(y0, y1);
            *(__half2*)(o1 + N) = __floats2half2_rn(y2, y3);
        }
    }
}

__device__ __forceinline__ void l2_body(
    char* sm, const __half* __restrict__ A, const __half* __restrict__ Bw,
    const float* __restrict__ bias, float* __restrict__ C, int K, int bnb, int bmb) {
    const uint32_t smb = smem_u32(sm);
    const int tid = threadIdx.x;
    const int wid = tid >> 5, lane = tid & 31;
    const int wm = wid >> 2, wn = wid & 3;
    const int g = lane >> 2, tq = lane & 3;
    const int lm = lane & 15, l16 = lane >> 4, fx = lane & 7;

    const int bm = bmb * 64;
    const int bn = bnb * 128;
    const int nch = K / 64;

    const int crow = tid >> 3;
    const int cslot = tid & 7;
    const uint32_t swz16 = (uint32_t)((cslot ^ (crow & 7)) << 4);
    const __half* Agb = A  + (size_t)(bm + crow) * K + cslot * 8;
    const __half* Bgb = Bw + (size_t)(bn + crow) * K + cslot * 8;

    float acc[2][4][4];
#pragma unroll
    for (int mt = 0; mt < 2; mt++)
#pragma unroll
        for (int nt = 0; nt < 4; nt++)
#pragma unroll
            for (int r = 0; r < 4; r++) acc[mt][nt][r] = 0.0f;

    auto issue = [&](int c) {
        const uint32_t base = smb + (uint32_t)(c & 1) * L2C;
#pragma unroll
        for (int it = 0; it < 2; it++)
            cp16(base + (uint32_t)(crow + it * 32) * 128 + swz16,
                 Agb + (size_t)it * 32 * K + c * 64);
#pragma unroll
        for (int it = 0; it < 4; it++)
            cp16(base + L2C_A + (uint32_t)(crow + it * 32) * 128 + swz16,
                 Bgb + (size_t)it * 32 * K + c * 64);
        asm volatile("cp.async.commit_group;" ::: "memory");
    };

    issue(0);

    const uint32_t a_row = (uint32_t)(wm * 32 + lm) * 128;
    const uint32_t b_row = (uint32_t)(wn * 32 + lm) * 128;

    for (int c = 0; c < nch; c++) {
        asm volatile("cp.async.wait_group 0;" ::: "memory");
        __syncthreads();
        if (c + 1 < nch) issue(c + 1);
        const uint32_t cb = smb + (uint32_t)(c & 1) * L2C;

#pragma unroll
        for (int kk = 0; kk < 4; kk++) {
            const uint32_t kslot = (uint32_t)(((kk * 2 + l16) ^ fx) << 4);
            uint32_t af[2][4];
            ldm_x4(af[0], cb + a_row + kslot);
            ldm_x4(af[1], cb + a_row + 16 * 128 + kslot);
            uint32_t bf[4][2];
#pragma unroll
            for (int p = 0; p < 2; p++) {
                uint32_t r[4];
                ldm_x4(r, cb + L2C_A + b_row + (uint32_t)(p * 16) * 128 + kslot);
                bf[2 * p][0] = r[0]; bf[2 * p + 1][0] = r[1];
                bf[2 * p][1] = r[2]; bf[2 * p + 1][1] = r[3];
            }
#pragma unroll
            for (int mt = 0; mt < 2; mt++)
#pragma unroll
                for (int nt = 0; nt < 4; nt++)
                    mma_f16(acc[mt][nt], af[mt], bf[nt]);
        }
    }

#pragma unroll
    for (int mt = 0; mt < 2; mt++) {
        const int row0 = bm + wm * 32 + mt * 16 + g;
#pragma unroll
        for (int nt = 0; nt < 4; nt++) {
            const int col = bn + wn * 32 + nt * 8 + 2 * tq;
            const float bv0 = bias[col], bv1 = bias[col + 1];
            const float v0 = ftanh(acc[mt][nt][0] + bv0);
            const float v1 = ftanh(acc[mt][nt][1] + bv1);
            const float v2 = ftanh(acc[mt][nt][2] + bv0);
            const float v3 = ftanh(acc[mt][nt][3] + bv1);
            const int t0 = row0 >> 6, b0 = row0 & 63;
            const int r1 = row0 + 8;
            const int t1 = r1 >> 6, b1 = r1 & 63;
            *(float2*)(C + (size_t)b0 * (STEPS * ACTION_DIM) + t0 * ACTION_DIM + col) =
                make_float2(v0, v1);
            *(float2*)(C + (size_t)b1 * (STEPS * ACTION_DIM) + t1 * ACTION_DIM + col) =
                make_float2(v2, v3);
        }
    }
}

// ---------------- fused 3-layer pipeline kernel (R11 structure) ----------------
// blocks [0,1024): L0 tiles (bn = b%16, bm = b/16), signal g_c0[bm]
// blocks [1024,1536): L1 tiles (bn = i%8, bm = i/8), wait g_c0[bm]==16, signal g_c1[bm]
// blocks [1536,1792): L2 tiles (bn = i%2, bm64 = i/2), wait g_c1[bm64>>1]==8
__global__ __launch_bounds__(256, 1)
void mlp_fused(const __half* __restrict__ st, const __half* __restrict__ B0,
               const float* __restrict__ b0r, const float* __restrict__ b0i,
               __half* __restrict__ a1,
               const __half* __restrict__ B1,
               const float* __restrict__ b1r, const float* __restrict__ b1i,
               __half* __restrict__ a2,
               const __half* __restrict__ P2, const float* __restrict__ b2r,
               float* __restrict__ out) {
    extern __shared__ char sm[];
    const int b = blockIdx.x;
    if (b < 1024) {
        const int bn = b & 15, bm = b >> 4;
        kar_body(sm, st, B0, b0r, b0i, a1, 512, 1024, bn, bm);
        sig_cnt(&g_c0[bm]);
    } else if (b < 1536) {
        const int i = b - 1024;
        const int bn = i & 7, bm = i >> 3;
        wait_cnt(&g_c0[bm], 16);
        kar_body(sm, a1, B1, b1r, b1i, a2, 1024, 512, bn, bm);
        sig_cnt(&g_c1[bm]);
    } else {
        const int i = b - 1536;
        const int bn = i & 1, bm64 = i >> 1;
        wait_cnt(&g_c1[bm64 >> 1], 8);
        l2_body(sm, a2, P2, b2r, out, 1024, bn, bm64);
    }
}

// ---------------- launch ----------------
extern "C" void kernel_launch(void* const* d_in, const int* in_sizes, int n_in,
                              void* d_out, int out_size) {
    const float* z     = (const float*)d_in[0];
    const float* omega = (const float*)d_in[1];
    const float* bpar  = (const float*)d_in[2];
    const float* W0r = (const float*)d_in[3];
    const float* W0i = (const float*)d_in[4];
    const float* b0r = (const float*)d_in[5];
    const float* b0i = (const float*)d_in[6];
    const float* W1r = (const float*)d_in[7];
    const float* W1i = (const float*)d_in[8];
    const float* b1r = (const float*)d_in[9];
    const float* b1i = (const float*)d_in[10];
    const float* W2r = (const float*)d_in[11];
    const float* W2i = (const float*)d_in[12];
    const float* b2r = (const float*)d_in[13];

    float* out = (float*)d_out;                                 // (64, 128, 256)
    float* out_z1 = out + (size_t)BATCH * STEPS * ACTION_DIM;   // (64, 1024)

    __half *B0, *B1, *P2, *st, *a1, *a2;
    cudaGetSymbolAddress((void**)&B0, g_B0k);
    cudaGetSymbolAddress((void**)&B1, g_B1k);
    cudaGetSymbolAddress((void**)&P2, g_P2h);
    cudaGetSymbolAddress((void**)&st, g_states_h);
    cudaGetSymbolAddress((void**)&a1, g_act1_h);
    cudaGetSymbolAddress((void**)&a2, g_act2_h);

    constexpr int SM_FUSED = 2 * KAR_BUF;    // 229376
    cudaFuncSetAttribute(mlp_fused, cudaFuncAttributeMaxDynamicSharedMemorySize, SM_FUSED);

    // prep: packs (z=0..2, counter reset in z=2) + hopf (z=3)
    prep_all<<<dim3(32, 32, 4), dim3(32, 8)>>>(z, omega, bpar,
                                               W0r, W0i, W1r, W1i, W2r, W2i,
                                               B0, B1, P2, st, out_z1);

    // fused L0 + L1 + L2 with per-row-block spin dependencies
    mlp_fused<<<1792, 256, SM_FUSED>>>(st, B0, b0r, b0i, a1,
                                       B1, b1r, b1i, a2,
                                       P2, b2r, out);
}

// round 14
// speedup vs baseline: 1.0180x; 1.0050x over previous
#include <cuda_runtime.h>
#include <cuda_fp16.h>
#include <math.h>
#include <cstdint>

#define DT 0.001f
#define STEPS 128
#define UNITS 512
#define BATCH 64
#define MROWS (STEPS * BATCH)   // 8192
#define ACTION_DIM 256

// ---------------- scratch ----------------
__device__ __half g_states_h[MROWS * 1024];   // [x(512) | y(512)]
__device__ __half g_act1_h[MROWS * 2048];     // [x(1024) | y(1024)]
__device__ __half g_act2_h[MROWS * 1024];     // [x(512) | y(512)]
__device__ __half g_B0k[3 * 1024 * 512];      // layer0 karatsuba B: [3][N=1024][K=512]
__device__ __half g_B1k[3 * 512 * 1024];      // layer1: [3][512][1024]
__device__ __half g_P2h[256 * 1024];          // layer2: [N=256][2K=1024]
__device__ int g_c0[64];                      // a1 row-block counters, target 16
__device__ int g_c1[64];                      // a2 row-block counters, target 8

__device__ __forceinline__ uint32_t smem_u32(const void* p) {
    uint32_t a;
    asm("{ .reg .u64 t; cvta.to.shared.u64 t, %1; cvt.u32.u64 %0, t; }" : "=r"(a) : "l"(p));
    return a;
}
__device__ __forceinline__ void cp16(uint32_t s, const void* g) {
    asm volatile("cp.async.cg.shared.global [%0], [%1], 16;" :: "r"(s), "l"(g));
}
__device__ __forceinline__ void ldm_x4(uint32_t* r, uint32_t addr) {
    asm volatile("ldmatrix.sync.aligned.m8n8.x4.shared.b16 {%0,%1,%2,%3}, [%4];"
                 : "=r"(r[0]), "=r"(r[1]), "=r"(r[2]), "=r"(r[3]) : "r"(addr));
}
__device__ __forceinline__ void mma_f16(float* c, const uint32_t* a, const uint32_t* b) {
    asm volatile(
        "mma.sync.aligned.m16n8k16.row.col.f32.f16.f16.f32 "
        "{%0,%1,%2,%3}, {%4,%5,%6,%7}, {%8,%9}, {%0,%1,%2,%3};"
        : "+f"(c[0]), "+f"(c[1]), "+f"(c[2]), "+f"(c[3])
        : "r"(a[0]), "r"(a[1]), "r"(a[2]), "r"(a[3]), "r"(b[0]), "r"(b[1]));
}
__device__ __forceinline__ uint32_t hadd2u(uint32_t a, uint32_t b) {
    __half2 r = __hadd2(*(__half2*)&a, *(__half2*)&b);
    return *(uint32_t*)&r;
}
// cross-CTA dependency primitives
__device__ __forceinline__ void wait_cnt(int* p, int target) {
    if (threadIdx.x == 0) {
        int v;
        for (;;) {
            asm volatile("ld.acquire.gpu.global.s32 %0, [%1];" : "=r"(v) : "l"(p));
            if (v >= target) break;
            __nanosleep(128);
        }
    }
    __syncthreads();
}
__device__ __forceinline__ void sig_cnt(int* p) {
    __threadfence();
    __syncthreads();
    if (threadIdx.x == 0) atomicAdd(p, 1);
}

// ---------------- prep: single-wave kernel (148 CTAs) ----------------
__device__ __forceinline__ void pack_kar_tile(
    const float* __restrict__ Wr, const float* __restrict__ Wi,
    __half* __restrict__ Bk, int K, int N, int k0, int n0,
    float (*tr)[33], float (*ti)[33], int tx, int ty0) {
#pragma unroll
    for (int i = 0; i < 4; i++) {
        int ty = ty0 + i * 8;
        tr[ty][tx] = Wr[(size_t)(k0 + ty) * N + n0 + tx];
        ti[ty][tx] = Wi[(size_t)(k0 + ty) * N + n0 + tx];
    }
    __syncthreads();
    const size_t NK = (size_t)N * K;
#pragma unroll
    for (int i = 0; i < 4; i++) {
        int ty = ty0 + i * 8;
        float wr = tr[tx][ty], wi = ti[tx][ty];
        size_t o = (size_t)(n0 + ty) * K + k0 + tx;
        Bk[o] = __float2half_rn(wr);
        Bk[NK + o] = __float2half_rn(wi - wr);
        Bk[2 * NK + o] = __float2half_rn(wr + wi);
    }
    __syncthreads();
}
__device__ __forceinline__ void pack_half_tile(
    const float* __restrict__ Wr, const float* __restrict__ Wi,
    __half* __restrict__ PT, int K, int N, int k0, int n0,
    float (*tile)[33], int tx, int ty0) {
#pragma unroll
    for (int i = 0; i < 4; i++) {
        int ty = ty0 + i * 8;
        int k = k0 + ty;
        float v = (k < K) ? Wr[(size_t)k * N + n0 + tx] : -Wi[(size_t)(k - K) * N + n0 + tx];
        tile[ty][tx] = v;
    }
    __syncthreads();
#pragma unroll
    for (int i = 0; i < 4; i++) {
        int ty = ty0 + i * 8;
        PT[(size_t)(n0 + ty) * (2 * K) + k0 + tx] = __float2half_rn(tile[tx][ty]);
    }
    __syncthreads();
}
__device__ __forceinline__ void hopf1d(
    int blk, const float* __restrict__ z0, const float* __restrict__ omega,
    const float* __restrict__ bpar, __half* __restrict__ states,
    float* __restrict__ out_z1) {
    int tid = blk * 256 + threadIdx.x;              // 0..16383
    int bi = tid >> 8;
    int i0 = tid & 255;
    int i1 = i0 + 256;
    const float om = omega[bi];
    float x0 = z0[bi * 1024 + i0],          y0 = z0[bi * 1024 + UNITS + i0];
    float x1 = z0[bi * 1024 + i1],          y1 = z0[bi * 1024 + UNITS + i1];
    const float w0 = om * (float)(i0 + 1),  w1 = om * (float)(i1 + 1);
    const float b0 = bpar[bi * UNITS + i0], b1 = bpar[bi * UNITS + i1];
#pragma unroll 4
    for (int t = 0; t < STEPS; t++) {
        float r20 = x0 * x0 + y0 * y0;
        float r21 = x1 * x1 + y1 * y1;
        float g0 = b0 - r20, g1 = b1 - r21;
        float dx0 = g0 * x0 - w0 * y0, dy0 = g0 * y0 + w0 * x0;
        float dx1 = g1 * x1 - w1 * y1, dy1 = g1 * y1 + w1 * x1;
        x0 += DT * dx0; y0 += DT * dy0;
        x1 += DT * dx1; y1 += DT * dy1;
        __half* row = states + ((size_t)(t * BATCH + bi)) * 1024;
        row[i0] = __float2half_rn(x0);
        row[i1] = __float2half_rn(x1);
        row[UNITS + i0] = __float2half_rn(y0);
        row[UNITS + i1] = __float2half_rn(y1);
        if (t == 0) {
            out_z1[bi * 1024 + i0] = x0;
            out_z1[bi * 1024 + i1] = x1;
            out_z1[bi * 1024 + UNITS + i0] = y0;
            out_z1[bi * 1024 + UNITS + i1] = y1;
        }
    }
}
// 148 CTAs: [0,64) hopf; [64,104) B0 workers; [104,136) B1 workers; [136,148) P2 + reset
__global__ __launch_bounds__(256)
void prep148(const float* z, const float* omega, const float* bpar,
             const float* W0r, const float* W0i,
             const float* W1r, const float* W1i,
             const float* W2r, const float* W2i,
             __half* B0, __half* B1, __half* P2,
             __half* states, float* out_z1) {
    __shared__ float t1[32][33], t2[32][33];
    const int b = blockIdx.x;
    const int tid = threadIdx.x;
    const int tx = tid & 31, ty0 = tid >> 5;
    if (b < 64) {
        hopf1d(b, z, omega, bpar, states, out_z1);
    } else if (b < 104) {
        for (int tt = b - 64; tt < 512; tt += 40)
            pack_kar_tile(W0r, W0i, B0, 512, 1024,
                          (tt & 15) * 32, (tt >> 4) * 32, t1, t2, tx, ty0);
    } else if (b < 136) {
        for (int tt = b - 104; tt < 512; tt += 32)
            pack_kar_tile(W1r, W1i, B1, 1024, 512,
                          (tt & 31) * 32, (tt >> 5) * 32, t1, t2, tx, ty0);
    } else {
        if (b == 136 && tid < 64) { g_c0[tid] = 0; g_c1[tid] = 0; }
        for (int tt = b - 136; tt < 256; tt += 12)
            pack_half_tile(W2r, W2i, P2, 512, 256,
                           (tt & 31) * 32, (tt >> 5) * 32, t1, tx, ty0);
    }
}

// ---------------- fused GEMM pipeline bodies (R11, tanhf) ----------------
#define KAR_BUF 114688   // per-buffer smem: Ax 32K + Ay 32K + B 48K
#define L2C_A  (64 * 128)
#define L2C    (L2C_A + 128 * 128)

__device__ __forceinline__ void kar_body(
    char* sm, const __half* __restrict__ Act, const __half* __restrict__ Bk,
    const float* __restrict__ br, const float* __restrict__ bi,
    __half* __restrict__ Out, int K, int N, int bnb, int bmb) {
    const uint32_t smb = smem_u32(sm);
    const int tid = threadIdx.x;
    const int wid = tid >> 5, lane = tid & 31;
    const int wm = wid >> 1, wn = wid & 1;
    const int g = lane >> 2, tq = lane & 3;
    const int lm = lane & 15, l16 = lane >> 4, fx = lane & 7;

    const int bm = bmb * 128;
    const int bn = bnb * 64;
    const int nch = K / 128;
    const int K2 = 2 * K;
    const size_t NK = (size_t)N * K;

    const int crow = tid >> 3;
    const int cslot = tid & 7;
    const uint32_t swz16 = (uint32_t)((cslot ^ (crow & 7)) << 4);

    float acc1[2][4][4], acc2[2][4][4], acc3[2][4][4];
#pragma unroll
    for (int mt = 0; mt < 2; mt++)
#pragma unroll
        for (int nt = 0; nt < 4; nt++)
#pragma unroll
            for (int r = 0; r < 4; r++) {
                acc1[mt][nt][r] = 0.0f; acc2[mt][nt][r] = 0.0f; acc3[mt][nt][r] = 0.0f;
            }

    auto issue = [&](int c) {
        const uint32_t base = smb + (uint32_t)(c & 1) * KAR_BUF;
#pragma unroll
        for (int op = 0; op < 2; op++)
#pragma unroll
            for (int pan = 0; pan < 2; pan++)
#pragma unroll
                for (int it = 0; it < 4; it++) {
                    int row = crow + it * 32;
                    uint32_t s = base + op * 32768 + pan * 16384 + (uint32_t)row * 128 + swz16;
                    const __half* gp = Act + (size_t)(bm + row) * K2 + op * K +
                                       c * 128 + pan * 64 + cslot * 8;
                    cp16(s, gp);
                }
#pragma unroll
        for (int mat = 0; mat < 3; mat++)
#pragma unroll
            for (int pan = 0; pan < 2; pan++)
#pragma unroll
                for (int it = 0; it < 2; it++) {
                    int row = crow + it * 32;
                    uint32_t s = base + 65536 + mat * 16384 + pan * 8192 +
                                 (uint32_t)row * 128 + swz16;
                    const __half* gp = Bk + (size_t)mat * NK + (size_t)(bn + row) * K +
                                       c * 128 + pan * 64 + cslot * 8;
                    cp16(s, gp);
                }
        asm volatile("cp.async.commit_group;" ::: "memory");
    };

    issue(0);

    const uint32_t a_row = (uint32_t)(wm * 32 + lm) * 128;
    const uint32_t b_row = (uint32_t)(wn * 32 + lm) * 128;

    for (int c = 0; c < nch; c++) {
        asm volatile("cp.async.wait_group 0;" ::: "memory");
        __syncthreads();
        if (c + 1 < nch) issue(c + 1);
        const uint32_t cb = smb + (uint32_t)(c & 1) * KAR_BUF;

#pragma unroll
        for (int kk = 0; kk < 8; kk++) {
            const int pan = kk >> 2, ks = kk & 3;
            const uint32_t kslot = (uint32_t)(((ks * 2 + l16) ^ fx) << 4);
            uint32_t af[2][2][4];
            const uint32_t ab = cb + pan * 16384 + a_row + kslot;
            ldm_x4(af[0][0], ab);
            ldm_x4(af[0][1], ab + 16 * 128);
            ldm_x4(af[1][0], ab + 32768);
            ldm_x4(af[1][1], ab + 32768 + 16 * 128);
            uint32_t bf[3][4][2];
            const uint32_t bb = cb + 65536 + pan * 8192 + b_row + kslot;
#pragma unroll
            for (int mat = 0; mat < 3; mat++) {
                uint32_t r[4];
                ldm_x4(r, bb + mat * 16384);
                bf[mat][0][0] = r[0]; bf[mat][1][0] = r[1];
                bf[mat][0][1] = r[2]; bf[mat][1][1] = r[3];
                ldm_x4(r, bb + mat * 16384 + 16 * 128);
                bf[mat][2][0] = r[0]; bf[mat][3][0] = r[1];
                bf[mat][2][1] = r[2]; bf[mat][3][1] = r[3];
            }
            uint32_t as[2][4];
#pragma unroll
            for (int mt = 0; mt < 2; mt++)
#pragma unroll
                for (int i = 0; i < 4; i++)
                    as[mt][i] = hadd2u(af[0][mt][i], af[1][mt][i]);
#pragma unroll
            for (int mt = 0; mt < 2; mt++)
#pragma unroll
                for (int nt = 0; nt < 4; nt++) {
                    mma_f16(acc1[mt][nt], as[mt],    bf[0][nt]);
                    mma_f16(acc2[mt][nt], af[0][mt], bf[1][nt]);
                    mma_f16(acc3[mt][nt], af[1][mt], bf[2][nt]);
                }
        }
    }

#pragma unroll
    for (int mt = 0; mt < 2; mt++) {
        const int row0 = bm + wm * 32 + mt * 16 + g;
#pragma unroll
        for (int nt = 0; nt < 4; nt++) {
            const int col = bn + wn * 32 + nt * 8 + 2 * tq;
            const float br0 = br[col], br1 = br[col + 1];
            const float bi0 = bi[col], bi1 = bi[col + 1];
            const float* a1 = acc1[mt][nt];
            const float* a2 = acc2[mt][nt];
            const float* a3 = acc3[mt][nt];
            const float x0 = tanhf(a1[0] - a3[0] + br0);
            const float x1 = tanhf(a1[1] - a3[1] + br1);
            const float x2 = tanhf(a1[2] - a3[2] + br0);
            const float x3 = tanhf(a1[3] - a3[3] + br1);
            const float y0 = tanhf(a1[0] + a2[0] + bi0);
            const float y1 = tanhf(a1[1] + a2[1] + bi1);
            const float y2 = tanhf(a1[2] + a2[2] + bi0);
            const float y3 = tanhf(a1[3] + a2[3] + bi1);
            __half* o0 = Out + (size_t)row0 * (2 * N) + col;
            __half* o1 = Out + (size_t)(row0 + 8) * (2 * N) + col;
            *(__half2*)o0 = __floats2half2_rn(x0, x1);
            *(__half2*)o1 = __floats2half2_rn(x2, x3);
            *(__half2*)(o0 + N) = __floats2half2_rn(y0, y1);
            *(__half2*)(o1 + N) = __floats2half2_rn(y2, y3);
        }
    }
}

__device__ __forceinline__ void l2_body(
    char* sm, const __half* __restrict__ A, const __half* __restrict__ Bw,
    const float* __restrict__ bias, float* __restrict__ C, int K, int bnb, int bmb) {
    const uint32_t smb = smem_u32(sm);
    const int tid = threadIdx.x;
    const int wid = tid >> 5, lane = tid & 31;
    const int wm = wid >> 2, wn = wid & 3;
    const int g = lane >> 2, tq = lane & 3;
    const int lm = lane & 15, l16 = lane >> 4, fx = lane & 7;

    const int bm = bmb * 64;
    const int bn = bnb * 128;
    const int nch = K / 64;

    const int crow = tid >> 3;
    const int cslot = tid & 7;
    const uint32_t swz16 = (uint32_t)((cslot ^ (crow & 7)) << 4);
    const __half* Agb = A  + (size_t)(bm + crow) * K + cslot * 8;
    const __half* Bgb = Bw + (size_t)(bn + crow) * K + cslot * 8;

    float acc[2][4][4];
#pragma unroll
    for (int mt = 0; mt < 2; mt++)
#pragma unroll
        for (int nt = 0; nt < 4; nt++)
#pragma unroll
            for (int r = 0; r < 4; r++) acc[mt][nt][r] = 0.0f;

    auto issue = [&](int c) {
        const uint32_t base = smb + (uint32_t)(c & 1) * L2C;
#pragma unroll
        for (int it = 0; it < 2; it++)
            cp16(base + (uint32_t)(crow + it * 32) * 128 + swz16,
                 Agb + (size_t)it * 32 * K + c * 64);
#pragma unroll
        for (int it = 0; it < 4; it++)
            cp16(base + L2C_A + (uint32_t)(crow + it * 32) * 128 + swz16,
                 Bgb + (size_t)it * 32 * K + c * 64);
        asm volatile("cp.async.commit_group;" ::: "memory");
    };

    issue(0);

    const uint32_t a_row = (uint32_t)(wm * 32 + lm) * 128;
    const uint32_t b_row = (uint32_t)(wn * 32 + lm) * 128;

    for (int c = 0; c < nch; c++) {
        asm volatile("cp.async.wait_group 0;" ::: "memory");
        __syncthreads();
        if (c + 1 < nch) issue(c + 1);
        const uint32_t cb = smb + (uint32_t)(c & 1) * L2C;

#pragma unroll
        for (int kk = 0; kk < 4; kk++) {
            const uint32_t kslot = (uint32_t)(((kk * 2 + l16) ^ fx) << 4);
            uint32_t af[2][4];
            ldm_x4(af[0], cb + a_row + kslot);
            ldm_x4(af[1], cb + a_row + 16 * 128 + kslot);
            uint32_t bf[4][2];
#pragma unroll
            for (int p = 0; p < 2; p++) {
                uint32_t r[4];
                ldm_x4(r, cb + L2C_A + b_row + (uint32_t)(p * 16) * 128 + kslot);
                bf[2 * p][0] = r[0]; bf[2 * p + 1][0] = r[1];
                bf[2 * p][1] = r[2]; bf[2 * p + 1][1] = r[3];
            }
#pragma unroll
            for (int mt = 0; mt < 2; mt++)
#pragma unroll
                for (int nt = 0; nt < 4; nt++)
                    mma_f16(acc[mt][nt], af[mt], bf[nt]);
        }
    }

#pragma unroll
    for (int mt = 0; mt < 2; mt++) {
        const int row0 = bm + wm * 32 + mt * 16 + g;
#pragma unroll
        for (int nt = 0; nt < 4; nt++) {
            const int col = bn + wn * 32 + nt * 8 + 2 * tq;
            const float bv0 = bias[col], bv1 = bias[col + 1];
            const float v0 = tanhf(acc[mt][nt][0] + bv0);
            const float v1 = tanhf(acc[mt][nt][1] + bv1);
            const float v2 = tanhf(acc[mt][nt][2] + bv0);
            const float v3 = tanhf(acc[mt][nt][3] + bv1);
            const int t0 = row0 >> 6, b0 = row0 & 63;
            const int r1 = row0 + 8;
            const int t1 = r1 >> 6, b1 = r1 & 63;
            *(float2*)(C + (size_t)b0 * (STEPS * ACTION_DIM) + t0 * ACTION_DIM + col) =
                make_float2(v0, v1);
            *(float2*)(C + (size_t)b1 * (STEPS * ACTION_DIM) + t1 * ACTION_DIM + col) =
                make_float2(v2, v3);
        }
    }
}

// ---------------- fused 3-layer pipeline kernel (R11 structure) ----------------
__global__ __launch_bounds__(256, 1)
void mlp_fused(const __half* __restrict__ st, const __half* __restrict__ B0,
               const float* __restrict__ b0r, const float* __restrict__ b0i,
               __half* __restrict__ a1,
               const __half* __restrict__ B1,
               const float* __restrict__ b1r, const float* __restrict__ b1i,
               __half* __restrict__ a2,
               const __half* __restrict__ P2, const float* __restrict__ b2r,
               float* __restrict__ out) {
    extern __shared__ char sm[];
    const int b = blockIdx.x;
    if (b < 1024) {
        const int bn = b & 15, bm = b >> 4;
        kar_body(sm, st, B0, b0r, b0i, a1, 512, 1024, bn, bm);
        sig_cnt(&g_c0[bm]);
    } else if (b < 1536) {
        const int i = b - 1024;
        const int bn = i & 7, bm = i >> 3;
        wait_cnt(&g_c0[bm], 16);
        kar_body(sm, a1, B1, b1r, b1i, a2, 1024, 512, bn, bm);
        sig_cnt(&g_c1[bm]);
    } else {
        const int i = b - 1536;
        const int bn = i & 1, bm64 = i >> 1;
        wait_cnt(&g_c1[bm64 >> 1], 8);
        l2_body(sm, a2, P2, b2r, out, 1024, bn, bm64);
    }
}

// ---------------- launch ----------------
extern "C" void kernel_launch(void* const* d_in, const int* in_sizes, int n_in,
                              void* d_out, int out_size) {
    const float* z     = (const float*)d_in[0];
    const float* omega = (const float*)d_in[1];
    const float* bpar  = (const float*)d_in[2];
    const float* W0r = (const float*)d_in[3];
    const float* W0i = (const float*)d_in[4];
    const float* b0r = (const float*)d_in[5];
    const float* b0i = (const float*)d_in[6];
    const float* W1r = (const float*)d_in[7];
    const float* W1i = (const float*)d_in[8];
    const float* b1r = (const float*)d_in[9];
    const float* b1i = (const float*)d_in[10];
    const float* W2r = (const float*)d_in[11];
    const float* W2i = (const float*)d_in[12];
    const float* b2r = (const float*)d_in[13];

    float* out = (float*)d_out;                                 // (64, 128, 256)
    float* out_z1 = out + (size_t)BATCH * STEPS * ACTION_DIM;   // (64, 1024)

    __half *B0, *B1, *P2, *st, *a1, *a2;
    cudaGetSymbolAddress((void**)&B0, g_B0k);
    cudaGetSymbolAddress((void**)&B1, g_B1k);
    cudaGetSymbolAddress((void**)&P2, g_P2h);
    cudaGetSymbolAddress((void**)&st, g_states_h);
    cudaGetSymbolAddress((void**)&a1, g_act1_h);
    cudaGetSymbolAddress((void**)&a2, g_act2_h);

    constexpr int SM_FUSED = 2 * KAR_BUF;    // 229376
    cudaFuncSetAttribute(mlp_fused, cudaFuncAttributeMaxDynamicSharedMemorySize, SM_FUSED);

    // single-wave prep: hopf + packs + counter reset (148 CTAs, tiny smem)
    prep148<<<148, 256>>>(z, omega, bpar,
                          W0r, W0i, W1r, W1i, W2r, W2i,
                          B0, B1, P2, st, out_z1);

    // fused L0 + L1 + L2 with per-row-block spin dependencies
    mlp_fused<<<1792, 256, SM_FUSED>>>(st, B0, b0r, b0i, a1,
                                       B1, b1r, b1i, a2,
                                       P2, b2r, out);
}

// round 15
// speedup vs baseline: 1.0786x; 1.0595x over previous
#include <cuda_runtime.h>
#include <cuda_fp16.h>
#include <math.h>
#include <cstdint>

#define DT 0.001f
#define STEPS 128
#define UNITS 512
#define BATCH 64
#define MROWS (STEPS * BATCH)   // 8192
#define ACTION_DIM 256

// ---------------- scratch ----------------
__device__ __half g_states_h[MROWS * 1024];   // [x(512) | y(512)]
__device__ __half g_act1_h[MROWS * 2048];     // [x(1024) | y(1024)]
__device__ __half g_act2_h[MROWS * 1024];     // [x(512) | y(512)]
__device__ __half g_B0k[3 * 1024 * 512];      // layer0 karatsuba B: [3][N=1024][K=512]
__device__ __half g_B1k[3 * 512 * 1024];      // layer1: [3][512][1024]
__device__ __half g_P2h[256 * 1024];          // layer2: [N=256][2K=1024]
__device__ int g_c0[64];                      // a1 row-block counters, target 16
__device__ int g_c1[64];                      // a2 row-block counters, target 8

__device__ __forceinline__ uint32_t smem_u32(const void* p) {
    uint32_t a;
    asm("{ .reg .u64 t; cvta.to.shared.u64 t, %1; cvt.u32.u64 %0, t; }" : "=r"(a) : "l"(p));
    return a;
}
__device__ __forceinline__ void cp16(uint32_t s, const void* g) {
    asm volatile("cp.async.cg.shared.global [%0], [%1], 16;" :: "r"(s), "l"(g));
}
__device__ __forceinline__ void ldm_x4(uint32_t* r, uint32_t addr) {
    asm volatile("ldmatrix.sync.aligned.m8n8.x4.shared.b16 {%0,%1,%2,%3}, [%4];"
                 : "=r"(r[0]), "=r"(r[1]), "=r"(r[2]), "=r"(r[3]) : "r"(addr));
}
__device__ __forceinline__ void mma_f16(float* c, const uint32_t* a, const uint32_t* b) {
    asm volatile(
        "mma.sync.aligned.m16n8k16.row.col.f32.f16.f16.f32 "
        "{%0,%1,%2,%3}, {%4,%5,%6,%7}, {%8,%9}, {%0,%1,%2,%3};"
        : "+f"(c[0]), "+f"(c[1]), "+f"(c[2]), "+f"(c[3])
        : "r"(a[0]), "r"(a[1]), "r"(a[2]), "r"(a[3]), "r"(b[0]), "r"(b[1]));
}
__device__ __forceinline__ uint32_t hadd2u(uint32_t a, uint32_t b) {
    __half2 r = __hadd2(*(__half2*)&a, *(__half2*)&b);
    return *(uint32_t*)&r;
}
// cross-CTA dependency primitives
__device__ __forceinline__ void wait_cnt(int* p, int target) {
    if (threadIdx.x == 0) {
        int v;
        for (;;) {
            asm volatile("ld.acquire.gpu.global.s32 %0, [%1];" : "=r"(v) : "l"(p));
            if (v >= target) break;
            __nanosleep(128);
        }
    }
    __syncthreads();
}
__device__ __forceinline__ void sig_cnt(int* p) {
    __threadfence();
    __syncthreads();
    if (threadIdx.x == 0) atomicAdd(p, 1);
}

// ---------------- prep: flat grid, one tile per CTA ----------------
__device__ __forceinline__ void pack_kar_tile(
    const float* __restrict__ Wr, const float* __restrict__ Wi,
    __half* __restrict__ Bk, int K, int N, int k0, int n0,
    float (*tr)[33], float (*ti)[33], int tx, int ty0) {
#pragma unroll
    for (int i = 0; i < 4; i++) {
        int ty = ty0 + i * 8;
        tr[ty][tx] = Wr[(size_t)(k0 + ty) * N + n0 + tx];
        ti[ty][tx] = Wi[(size_t)(k0 + ty) * N + n0 + tx];
    }
    __syncthreads();
    const size_t NK = (size_t)N * K;
#pragma unroll
    for (int i = 0; i < 4; i++) {
        int ty = ty0 + i * 8;
        float wr = tr[tx][ty], wi = ti[tx][ty];
        size_t o = (size_t)(n0 + ty) * K + k0 + tx;
        Bk[o] = __float2half_rn(wr);
        Bk[NK + o] = __float2half_rn(wi - wr);
        Bk[2 * NK + o] = __float2half_rn(wr + wi);
    }
}
__device__ __forceinline__ void pack_half_tile(
    const float* __restrict__ Wr, const float* __restrict__ Wi,
    __half* __restrict__ PT, int K, int N, int k0, int n0,
    float (*tile)[33], int tx, int ty0) {
#pragma unroll
    for (int i = 0; i < 4; i++) {
        int ty = ty0 + i * 8;
        int k = k0 + ty;
        float v = (k < K) ? Wr[(size_t)k * N + n0 + tx] : -Wi[(size_t)(k - K) * N + n0 + tx];
        tile[ty][tx] = v;
    }
    __syncthreads();
#pragma unroll
    for (int i = 0; i < 4; i++) {
        int ty = ty0 + i * 8;
        PT[(size_t)(n0 + ty) * (2 * K) + k0 + tx] = __float2half_rn(tile[tx][ty]);
    }
}
__device__ __forceinline__ void hopf1d(
    int blk, const float* __restrict__ z0, const float* __restrict__ omega,
    const float* __restrict__ bpar, __half* __restrict__ states,
    float* __restrict__ out_z1) {
    int tid = blk * 256 + threadIdx.x;              // 0..16383
    int bi = tid >> 8;
    int i0 = tid & 255;
    int i1 = i0 + 256;
    const float om = omega[bi];
    float x0 = z0[bi * 1024 + i0],          y0 = z0[bi * 1024 + UNITS + i0];
    float x1 = z0[bi * 1024 + i1],          y1 = z0[bi * 1024 + UNITS + i1];
    const float w0 = om * (float)(i0 + 1),  w1 = om * (float)(i1 + 1);
    const float b0 = bpar[bi * UNITS + i0], b1 = bpar[bi * UNITS + i1];
#pragma unroll 4
    for (int t = 0; t < STEPS; t++) {
        float r20 = x0 * x0 + y0 * y0;
        float r21 = x1 * x1 + y1 * y1;
        float g0 = b0 - r20, g1 = b1 - r21;
        float dx0 = g0 * x0 - w0 * y0, dy0 = g0 * y0 + w0 * x0;
        float dx1 = g1 * x1 - w1 * y1, dy1 = g1 * y1 + w1 * x1;
        x0 += DT * dx0; y0 += DT * dy0;
        x1 += DT * dx1; y1 += DT * dy1;
        __half* row = states + ((size_t)(t * BATCH + bi)) * 1024;
        row[i0] = __float2half_rn(x0);
        row[i1] = __float2half_rn(x1);
        row[UNITS + i0] = __float2half_rn(y0);
        row[UNITS + i1] = __float2half_rn(y1);
        if (t == 0) {
            out_z1[bi * 1024 + i0] = x0;
            out_z1[bi * 1024 + i1] = x1;
            out_z1[bi * 1024 + UNITS + i0] = y0;
            out_z1[bi * 1024 + UNITS + i1] = y1;
        }
    }
}
// 1344 CTAs, one tile each:
// [0,64) hopf; [64,576) B0 tiles; [576,832) P2 tiles (+reset); [832,1344) B1 tiles
__global__ __launch_bounds__(256)
void prep_flat(const float* z, const float* omega, const float* bpar,
               const float* W0r, const float* W0i,
               const float* W1r, const float* W1i,
               const float* W2r, const float* W2i,
               __half* B0, __half* B1, __half* P2,
               __half* states, float* out_z1) {
    __shared__ float t1[32][33], t2[32][33];
    const int b = blockIdx.x;
    const int tid = threadIdx.x;
    const int tx = tid & 31, ty0 = tid >> 5;
    if (b < 64) {
        hopf1d(b, z, omega, bpar, states, out_z1);
    } else if (b < 576) {
        const int tt = b - 64;                 // 512 tiles: K=512(16) x N=1024(32)
        pack_kar_tile(W0r, W0i, B0, 512, 1024, (tt & 15) * 32, (tt >> 4) * 32,
                      t1, t2, tx, ty0);
    } else if (b < 832) {
        if (b == 576 && tid < 64) { g_c0[tid] = 0; g_c1[tid] = 0; }
        const int tt = b - 576;                // 256 tiles: 2K=1024(32) x N=256(8)
        pack_half_tile(W2r, W2i, P2, 512, 256, (tt & 31) * 32, (tt >> 5) * 32,
                       t1, tx, ty0);
    } else {
        const int tt = b - 832;                // 512 tiles: K=1024(32) x N=512(16)
        pack_kar_tile(W1r, W1i, B1, 1024, 512, (tt & 31) * 32, (tt >> 5) * 32,
                      t1, t2, tx, ty0);
    }
}

// ---------------- fused GEMM pipeline bodies (R11, tanhf) ----------------
#define KAR_BUF 114688   // per-buffer smem: Ax 32K + Ay 32K + B 48K
#define L2C_A  (64 * 128)
#define L2C    (L2C_A + 128 * 128)

__device__ __forceinline__ void kar_body(
    char* sm, const __half* __restrict__ Act, const __half* __restrict__ Bk,
    const float* __restrict__ br, const float* __restrict__ bi,
    __half* __restrict__ Out, int K, int N, int bnb, int bmb) {
    const uint32_t smb = smem_u32(sm);
    const int tid = threadIdx.x;
    const int wid = tid >> 5, lane = tid & 31;
    const int wm = wid >> 1, wn = wid & 1;
    const int g = lane >> 2, tq = lane & 3;
    const int lm = lane & 15, l16 = lane >> 4, fx = lane & 7;

    const int bm = bmb * 128;
    const int bn = bnb * 64;
    const int nch = K / 128;
    const int K2 = 2 * K;
    const size_t NK = (size_t)N * K;

    const int crow = tid >> 3;
    const int cslot = tid & 7;
    const uint32_t swz16 = (uint32_t)((cslot ^ (crow & 7)) << 4);

    float acc1[2][4][4], acc2[2][4][4], acc3[2][4][4];
#pragma unroll
    for (int mt = 0; mt < 2; mt++)
#pragma unroll
        for (int nt = 0; nt < 4; nt++)
#pragma unroll
            for (int r = 0; r < 4; r++) {
                acc1[mt][nt][r] = 0.0f; acc2[mt][nt][r] = 0.0f; acc3[mt][nt][r] = 0.0f;
            }

    auto issue = [&](int c) {
        const uint32_t base = smb + (uint32_t)(c & 1) * KAR_BUF;
#pragma unroll
        for (int op = 0; op < 2; op++)
#pragma unroll
            for (int pan = 0; pan < 2; pan++)
#pragma unroll
                for (int it = 0; it < 4; it++) {
                    int row = crow + it * 32;
                    uint32_t s = base + op * 32768 + pan * 16384 + (uint32_t)row * 128 + swz16;
                    const __half* gp = Act + (size_t)(bm + row) * K2 + op * K +
                                       c * 128 + pan * 64 + cslot * 8;
                    cp16(s, gp);
                }
#pragma unroll
        for (int mat = 0; mat < 3; mat++)
#pragma unroll
            for (int pan = 0; pan < 2; pan++)
#pragma unroll
                for (int it = 0; it < 2; it++) {
                    int row = crow + it * 32;
                    uint32_t s = base + 65536 + mat * 16384 + pan * 8192 +
                                 (uint32_t)row * 128 + swz16;
                    const __half* gp = Bk + (size_t)mat * NK + (size_t)(bn + row) * K +
                                       c * 128 + pan * 64 + cslot * 8;
                    cp16(s, gp);
                }
        asm volatile("cp.async.commit_group;" ::: "memory");
    };

    issue(0);

    const uint32_t a_row = (uint32_t)(wm * 32 + lm) * 128;
    const uint32_t b_row = (uint32_t)(wn * 32 + lm) * 128;

    for (int c = 0; c < nch; c++) {
        asm volatile("cp.async.wait_group 0;" ::: "memory");
        __syncthreads();
        if (c + 1 < nch) issue(c + 1);
        const uint32_t cb = smb + (uint32_t)(c & 1) * KAR_BUF;

#pragma unroll
        for (int kk = 0; kk < 8; kk++) {
            const int pan = kk >> 2, ks = kk & 3;
            const uint32_t kslot = (uint32_t)(((ks * 2 + l16) ^ fx) << 4);
            uint32_t af[2][2][4];
            const uint32_t ab = cb + pan * 16384 + a_row + kslot;
            ldm_x4(af[0][0], ab);
            ldm_x4(af[0][1], ab + 16 * 128);
            ldm_x4(af[1][0], ab + 32768);
            ldm_x4(af[1][1], ab + 32768 + 16 * 128);
            uint32_t bf[3][4][2];
            const uint32_t bb = cb + 65536 + pan * 8192 + b_row + kslot;
#pragma unroll
            for (int mat = 0; mat < 3; mat++) {
                uint32_t r[4];
                ldm_x4(r, bb + mat * 16384);
                bf[mat][0][0] = r[0]; bf[mat][1][0] = r[1];
                bf[mat][0][1] = r[2]; bf[mat][1][1] = r[3];
                ldm_x4(r, bb + mat * 16384 + 16 * 128);
                bf[mat][2][0] = r[0]; bf[mat][3][0] = r[1];
                bf[mat][2][1] = r[2]; bf[mat][3][1] = r[3];
            }
            uint32_t as[2][4];
#pragma unroll
            for (int mt = 0; mt < 2; mt++)
#pragma unroll
                for (int i = 0; i < 4; i++)
                    as[mt][i] = hadd2u(af[0][mt][i], af[1][mt][i]);
#pragma unroll
            for (int mt = 0; mt < 2; mt++)
#pragma unroll
                for (int nt = 0; nt < 4; nt++) {
                    mma_f16(acc1[mt][nt], as[mt],    bf[0][nt]);
                    mma_f16(acc2[mt][nt], af[0][mt], bf[1][nt]);
                    mma_f16(acc3[mt][nt], af[1][mt], bf[2][nt]);
                }
        }
    }

#pragma unroll
    for (int mt = 0; mt < 2; mt++) {
        const int row0 = bm + wm * 32 + mt * 16 + g;
#pragma unroll
        for (int nt = 0; nt < 4; nt++) {
            const int col = bn + wn * 32 + nt * 8 + 2 * tq;
            const float br0 = br[col], br1 = br[col + 1];
            const float bi0 = bi[col], bi1 = bi[col + 1];
            const float* a1 = acc1[mt][nt];
            const float* a2 = acc2[mt][nt];
            const float* a3 = acc3[mt][nt];
            const float x0 = tanhf(a1[0] - a3[0] + br0);
            const float x1 = tanhf(a1[1] - a3[1] + br1);
            const float x2 = tanhf(a1[2] - a3[2] + br0);
            const float x3 = tanhf(a1[3] - a3[3] + br1);
            const float y0 = tanhf(a1[0] + a2[0] + bi0);
            const float y1 = tanhf(a1[1] + a2[1] + bi1);
            const float y2 = tanhf(a1[2] + a2[2] + bi0);
            const float y3 = tanhf(a1[3] + a2[3] + bi1);
            __half* o0 = Out + (size_t)row0 * (2 * N) + col;
            __half* o1 = Out + (size_t)(row0 + 8) * (2 * N) + col;
            *(__half2*)o0 = __floats2half2_rn(x0, x1);
            *(__half2*)o1 = __floats2half2_rn(x2, x3);
            *(__half2*)(o0 + N) = __floats2half2_rn(y0, y1);
            *(__half2*)(o1 + N) = __floats2half2_rn(y2, y3);
        }
    }
}

__device__ __forceinline__ void l2_body(
    char* sm, const __half* __restrict__ A, const __half* __restrict__ Bw,
    const float* __restrict__ bias, float* __restrict__ C, int K, int bnb, int bmb) {
    const uint32_t smb = smem_u32(sm);
    const int tid = threadIdx.x;
    const int wid = tid >> 5, lane = tid & 31;
    const int wm = wid >> 2, wn = wid & 3;
    const int g = lane >> 2, tq = lane & 3;
    const int lm = lane & 15, l16 = lane >> 4, fx = lane & 7;

    const int bm = bmb * 64;
    const int bn = bnb * 128;
    const int nch = K / 64;

    const int crow = tid >> 3;
    const int cslot = tid & 7;
    const uint32_t swz16 = (uint32_t)((cslot ^ (crow & 7)) << 4);
    const __half* Agb = A  + (size_t)(bm + crow) * K + cslot * 8;
    const __half* Bgb = Bw + (size_t)(bn + crow) * K + cslot * 8;

    float acc[2][4][4];
#pragma unroll
    for (int mt = 0; mt < 2; mt++)
#pragma unroll
        for (int nt = 0; nt < 4; nt++)
#pragma unroll
            for (int r = 0; r < 4; r++) acc[mt][nt][r] = 0.0f;

    auto issue = [&](int c) {
        const uint32_t base = smb + (uint32_t)(c & 1) * L2C;
#pragma unroll
        for (int it = 0; it < 2; it++)
            cp16(base + (uint32_t)(crow + it * 32) * 128 + swz16,
                 Agb + (size_t)it * 32 * K + c * 64);
#pragma unroll
        for (int it = 0; it < 4; it++)
            cp16(base + L2C_A + (uint32_t)(crow + it * 32) * 128 + swz16,
                 Bgb + (size_t)it * 32 * K + c * 64);
        asm volatile("cp.async.commit_group;" ::: "memory");
    };

    issue(0);

    const uint32_t a_row = (uint32_t)(wm * 32 + lm) * 128;
    const uint32_t b_row = (uint32_t)(wn * 32 + lm) * 128;

    for (int c = 0; c < nch; c++) {
        asm volatile("cp.async.wait_group 0;" ::: "memory");
        __syncthreads();
        if (c + 1 < nch) issue(c + 1);
        const uint32_t cb = smb + (uint32_t)(c & 1) * L2C;

#pragma unroll
        for (int kk = 0; kk < 4; kk++) {
            const uint32_t kslot = (uint32_t)(((kk * 2 + l16) ^ fx) << 4);
            uint32_t af[2][4];
            ldm_x4(af[0], cb + a_row + kslot);
            ldm_x4(af[1], cb + a_row + 16 * 128 + kslot);
            uint32_t bf[4][2];
#pragma unroll
            for (int p = 0; p < 2; p++) {
                uint32_t r[4];
                ldm_x4(r, cb + L2C_A + b_row + (uint32_t)(p * 16) * 128 + kslot);
                bf[2 * p][0] = r[0]; bf[2 * p + 1][0] = r[1];
                bf[2 * p][1] = r[2]; bf[2 * p + 1][1] = r[3];
            }
#pragma unroll
            for (int mt = 0; mt < 2; mt++)
#pragma unroll
                for (int nt = 0; nt < 4; nt++)
                    mma_f16(acc[mt][nt], af[mt], bf[nt]);
        }
    }

#pragma unroll
    for (int mt = 0; mt < 2; mt++) {
        const int row0 = bm + wm * 32 + mt * 16 + g;
#pragma unroll
        for (int nt = 0; nt < 4; nt++) {
            const int col = bn + wn * 32 + nt * 8 + 2 * tq;
            const float bv0 = bias[col], bv1 = bias[col + 1];
            const float v0 = tanhf(acc[mt][nt][0] + bv0);
            const float v1 = tanhf(acc[mt][nt][1] + bv1);
            const float v2 = tanhf(acc[mt][nt][2] + bv0);
            const float v3 = tanhf(acc[mt][nt][3] + bv1);
            const int t0 = row0 >> 6, b0 = row0 & 63;
            const int r1 = row0 + 8;
            const int t1 = r1 >> 6, b1 = r1 & 63;
            *(float2*)(C + (size_t)b0 * (STEPS * ACTION_DIM) + t0 * ACTION_DIM + col) =
                make_float2(v0, v1);
            *(float2*)(C + (size_t)b1 * (STEPS * ACTION_DIM) + t1 * ACTION_DIM + col) =
                make_float2(v2, v3);
        }
    }
}

// ---------------- fused 3-layer pipeline kernel (R11 structure) ----------------
__global__ __launch_bounds__(256, 1)
void mlp_fused(const __half* __restrict__ st, const __half* __restrict__ B0,
               const float* __restrict__ b0r, const float* __restrict__ b0i,
               __half* __restrict__ a1,
               const __half* __restrict__ B1,
               const float* __restrict__ b1r, const float* __restrict__ b1i,
               __half* __restrict__ a2,
               const __half* __restrict__ P2, const float* __restrict__ b2r,
               float* __restrict__ out) {
    extern __shared__ char sm[];
    const int b = blockIdx.x;
    if (b < 1024) {
        const int bn = b & 15, bm = b >> 4;
        kar_body(sm, st, B0, b0r, b0i, a1, 512, 1024, bn, bm);
        sig_cnt(&g_c0[bm]);
    } else if (b < 1536) {
        const int i = b - 1024;
        const int bn = i & 7, bm = i >> 3;
        wait_cnt(&g_c0[bm], 16);
        kar_body(sm, a1, B1, b1r, b1i, a2, 1024, 512, bn, bm);
        sig_cnt(&g_c1[bm]);
    } else {
        const int i = b - 1536;
        const int bn = i & 1, bm64 = i >> 1;
        wait_cnt(&g_c1[bm64 >> 1], 8);
        l2_body(sm, a2, P2, b2r, out, 1024, bn, bm64);
    }
}

// ---------------- launch ----------------
extern "C" void kernel_launch(void* const* d_in, const int* in_sizes, int n_in,
                              void* d_out, int out_size) {
    const float* z     = (const float*)d_in[0];
    const float* omega = (const float*)d_in[1];
    const float* bpar  = (const float*)d_in[2];
    const float* W0r = (const float*)d_in[3];
    const float* W0i = (const float*)d_in[4];
    const float* b0r = (const float*)d_in[5];
    const float* b0i = (const float*)d_in[6];
    const float* W1r = (const float*)d_in[7];
    const float* W1i = (const float*)d_in[8];
    const float* b1r = (const float*)d_in[9];
    const float* b1i = (const float*)d_in[10];
    const float* W2r = (const float*)d_in[11];
    const float* W2i = (const float*)d_in[12];
    const float* b2r = (const float*)d_in[13];

    float* out = (float*)d_out;                                 // (64, 128, 256)
    float* out_z1 = out + (size_t)BATCH * STEPS * ACTION_DIM;   // (64, 1024)

    __half *B0, *B1, *P2, *st, *a1, *a2;
    cudaGetSymbolAddress((void**)&B0, g_B0k);
    cudaGetSymbolAddress((void**)&B1, g_B1k);
    cudaGetSymbolAddress((void**)&P2, g_P2h);
    cudaGetSymbolAddress((void**)&st, g_states_h);
    cudaGetSymbolAddress((void**)&a1, g_act1_h);
    cudaGetSymbolAddress((void**)&a2, g_act2_h);

    constexpr int SM_FUSED = 2 * KAR_BUF;    // 229376
    cudaFuncSetAttribute(mlp_fused, cudaFuncAttributeMaxDynamicSharedMemorySize, SM_FUSED);

    // flat prep: one tile per CTA, hopf first (1344 CTAs, tiny smem)
    prep_flat<<<1344, 256>>>(z, omega, bpar,
                             W0r, W0i, W1r, W1i, W2r, W2i,
                             B0, B1, P2, st, out_z1);

    // fused L0 + L1 + L2 with per-row-block spin dependencies
    mlp_fused<<<1792, 256, SM_FUSED>>>(st, B0, b0r, b0i, a1,
                                       B1, b1r, b1i, a2,
                                       P2, b2r, out);
}

// round 16
// speedup vs baseline: 1.0796x; 1.0009x over previous
#include <cuda_runtime.h>
#include <cuda_fp16.h>
#include <math.h>
#include <cstdint>

#define DT 0.001f
#define STEPS 128
#define UNITS 512
#define BATCH 64
#define MROWS (STEPS * BATCH)   // 8192
#define ACTION_DIM 256

// ---------------- scratch ----------------
__device__ __half g_states_h[MROWS * 1024];   // [x(512) | y(512)]
__device__ __half g_act1_h[MROWS * 2048];     // [x(1024) | y(1024)]
__device__ __half g_act2_h[MROWS * 1024];     // [x(512) | y(512)]
__device__ __half g_B0k[3 * 1024 * 512];      // layer0 karatsuba B: [3][N=1024][K=512]
__device__ __half g_B1k[3 * 512 * 1024];      // layer1: [3][512][1024]
__device__ __half g_P2h[256 * 1024];          // layer2: [N=256][2K=1024]
__device__ int g_c0[64];                      // a1 row-block counters, target 16
__device__ int g_c1[64];                      // a2 row-block counters, target 8

__device__ __forceinline__ uint32_t smem_u32(const void* p) {
    uint32_t a;
    asm("{ .reg .u64 t; cvta.to.shared.u64 t, %1; cvt.u32.u64 %0, t; }" : "=r"(a) : "l"(p));
    return a;
}
__device__ __forceinline__ void cp16(uint32_t s, const void* g) {
    asm volatile("cp.async.cg.shared.global [%0], [%1], 16;" :: "r"(s), "l"(g));
}
__device__ __forceinline__ void ldm_x4(uint32_t* r, uint32_t addr) {
    asm volatile("ldmatrix.sync.aligned.m8n8.x4.shared.b16 {%0,%1,%2,%3}, [%4];"
                 : "=r"(r[0]), "=r"(r[1]), "=r"(r[2]), "=r"(r[3]) : "r"(addr));
}
__device__ __forceinline__ void mma_f16(float* c, const uint32_t* a, const uint32_t* b) {
    asm volatile(
        "mma.sync.aligned.m16n8k16.row.col.f32.f16.f16.f32 "
        "{%0,%1,%2,%3}, {%4,%5,%6,%7}, {%8,%9}, {%0,%1,%2,%3};"
        : "+f"(c[0]), "+f"(c[1]), "+f"(c[2]), "+f"(c[3])
        : "r"(a[0]), "r"(a[1]), "r"(a[2]), "r"(a[3]), "r"(b[0]), "r"(b[1]));
}
__device__ __forceinline__ uint32_t hadd2u(uint32_t a, uint32_t b) {
    __half2 r = __hadd2(*(__half2*)&a, *(__half2*)&b);
    return *(uint32_t*)&r;
}
// cross-CTA dependency primitives
__device__ __forceinline__ void wait_cnt(int* p, int target) {
    if (threadIdx.x == 0) {
        int v;
        for (;;) {
            asm volatile("ld.acquire.gpu.global.s32 %0, [%1];" : "=r"(v) : "l"(p));
            if (v >= target) break;
            __nanosleep(128);
        }
    }
    __syncthreads();
}
__device__ __forceinline__ void sig_cnt(int* p) {
    __threadfence();
    __syncthreads();
    if (threadIdx.x == 0) atomicAdd(p, 1);
}

// ---------------- prep: flat grid, one tile per CTA ----------------
__device__ __forceinline__ void pack_kar_tile(
    const float* __restrict__ Wr, const float* __restrict__ Wi,
    __half* __restrict__ Bk, int K, int N, int k0, int n0,
    float (*tr)[33], float (*ti)[33], int tx, int ty0) {
#pragma unroll
    for (int i = 0; i < 4; i++) {
        int ty = ty0 + i * 8;
        tr[ty][tx] = Wr[(size_t)(k0 + ty) * N + n0 + tx];
        ti[ty][tx] = Wi[(size_t)(k0 + ty) * N + n0 + tx];
    }
    __syncthreads();
    const size_t NK = (size_t)N * K;
#pragma unroll
    for (int i = 0; i < 4; i++) {
        int ty = ty0 + i * 8;
        float wr = tr[tx][ty], wi = ti[tx][ty];
        size_t o = (size_t)(n0 + ty) * K + k0 + tx;
        Bk[o] = __float2half_rn(wr);
        Bk[NK + o] = __float2half_rn(wi - wr);
        Bk[2 * NK + o] = __float2half_rn(wr + wi);
    }
}
__device__ __forceinline__ void pack_half_tile(
    const float* __restrict__ Wr, const float* __restrict__ Wi,
    __half* __restrict__ PT, int K, int N, int k0, int n0,
    float (*tile)[33], int tx, int ty0) {
#pragma unroll
    for (int i = 0; i < 4; i++) {
        int ty = ty0 + i * 8;
        int k = k0 + ty;
        float v = (k < K) ? Wr[(size_t)k * N + n0 + tx] : -Wi[(size_t)(k - K) * N + n0 + tx];
        tile[ty][tx] = v;
    }
    __syncthreads();
#pragma unroll
    for (int i = 0; i < 4; i++) {
        int ty = ty0 + i * 8;
        PT[(size_t)(n0 + ty) * (2 * K) + k0 + tx] = __float2half_rn(tile[tx][ty]);
    }
}
// hopf: each thread owns two ADJACENT units (2j, 2j+1) -> half2/float2 stores
__device__ __forceinline__ void hopf1d(
    int blk, const float* __restrict__ z0, const float* __restrict__ omega,
    const float* __restrict__ bpar, __half* __restrict__ states,
    float* __restrict__ out_z1) {
    int tid = blk * 256 + threadIdx.x;              // 0..16383
    int bi = tid >> 8;                              // batch
    int j = tid & 255;                              // unit pair
    int i0 = 2 * j, i1 = 2 * j + 1;
    const float om = omega[bi];
    float2 xz = *(const float2*)(z0 + bi * 1024 + i0);
    float2 yz = *(const float2*)(z0 + bi * 1024 + UNITS + i0);
    float x0 = xz.x, x1 = xz.y, y0 = yz.x, y1 = yz.y;
    const float w0 = om * (float)(i0 + 1), w1 = om * (float)(i1 + 1);
    const float b0 = bpar[bi * UNITS + i0], b1 = bpar[bi * UNITS + i1];
#pragma unroll 4
    for (int t = 0; t < STEPS; t++) {
        float r20 = x0 * x0 + y0 * y0;
        float r21 = x1 * x1 + y1 * y1;
        float g0 = b0 - r20, g1 = b1 - r21;
        float dx0 = g0 * x0 - w0 * y0, dy0 = g0 * y0 + w0 * x0;
        float dx1 = g1 * x1 - w1 * y1, dy1 = g1 * y1 + w1 * x1;
        x0 += DT * dx0; y0 += DT * dy0;
        x1 += DT * dx1; y1 += DT * dy1;
        __half* row = states + ((size_t)(t * BATCH + bi)) * 1024;
        *(__half2*)(row + i0) = __floats2half2_rn(x0, x1);
        *(__half2*)(row + UNITS + i0) = __floats2half2_rn(y0, y1);
        if (t == 0) {
            *(float2*)(out_z1 + bi * 1024 + i0) = make_float2(x0, x1);
            *(float2*)(out_z1 + bi * 1024 + UNITS + i0) = make_float2(y0, y1);
        }
    }
}
// 1344 CTAs, one tile each:
// [0,64) hopf; [64,576) B0 tiles; [576,832) P2 tiles (+reset); [832,1344) B1 tiles
__global__ __launch_bounds__(256)
void prep_flat(const float* z, const float* omega, const float* bpar,
               const float* W0r, const float* W0i,
               const float* W1r, const float* W1i,
               const float* W2r, const float* W2i,
               __half* B0, __half* B1, __half* P2,
               __half* states, float* out_z1) {
    __shared__ float t1[32][33], t2[32][33];
    const int b = blockIdx.x;
    const int tid = threadIdx.x;
    const int tx = tid & 31, ty0 = tid >> 5;
    if (b < 64) {
        hopf1d(b, z, omega, bpar, states, out_z1);
    } else if (b < 576) {
        const int tt = b - 64;                 // 512 tiles: K=512(16) x N=1024(32)
        pack_kar_tile(W0r, W0i, B0, 512, 1024, (tt & 15) * 32, (tt >> 4) * 32,
                      t1, t2, tx, ty0);
    } else if (b < 832) {
        if (b == 576 && tid < 64) { g_c0[tid] = 0; g_c1[tid] = 0; }
        const int tt = b - 576;                // 256 tiles: 2K=1024(32) x N=256(8)
        pack_half_tile(W2r, W2i, P2, 512, 256, (tt & 31) * 32, (tt >> 5) * 32,
                       t1, tx, ty0);
    } else {
        const int tt = b - 832;                // 512 tiles: K=1024(32) x N=512(16)
        pack_kar_tile(W1r, W1i, B1, 1024, 512, (tt & 31) * 32, (tt >> 5) * 32,
                      t1, t2, tx, ty0);
    }
}

// ---------------- fused GEMM pipeline bodies (R11, tanhf) ----------------
#define KAR_BUF 114688   // per-buffer smem: Ax 32K + Ay 32K + B 48K
#define L2C_A  (64 * 128)
#define L2C    (L2C_A + 128 * 128)

__device__ __forceinline__ void kar_body(
    char* sm, const __half* __restrict__ Act, const __half* __restrict__ Bk,
    const float* __restrict__ br, const float* __restrict__ bi,
    __half* __restrict__ Out, int K, int N, int bnb, int bmb) {
    const uint32_t smb = smem_u32(sm);
    const int tid = threadIdx.x;
    const int wid = tid >> 5, lane = tid & 31;
    const int wm = wid >> 1, wn = wid & 1;
    const int g = lane >> 2, tq = lane & 3;
    const int lm = lane & 15, l16 = lane >> 4, fx = lane & 7;

    const int bm = bmb * 128;
    const int bn = bnb * 64;
    const int nch = K / 128;
    const int K2 = 2 * K;
    const size_t NK = (size_t)N * K;

    const int crow = tid >> 3;
    const int cslot = tid & 7;
    const uint32_t swz16 = (uint32_t)((cslot ^ (crow & 7)) << 4);

    float acc1[2][4][4], acc2[2][4][4], acc3[2][4][4];
#pragma unroll
    for (int mt = 0; mt < 2; mt++)
#pragma unroll
        for (int nt = 0; nt < 4; nt++)
#pragma unroll
            for (int r = 0; r < 4; r++) {
                acc1[mt][nt][r] = 0.0f; acc2[mt][nt][r] = 0.0f; acc3[mt][nt][r] = 0.0f;
            }

    auto issue = [&](int c) {
        const uint32_t base = smb + (uint32_t)(c & 1) * KAR_BUF;
#pragma unroll
        for (int op = 0; op < 2; op++)
#pragma unroll
            for (int pan = 0; pan < 2; pan++)
#pragma unroll
                for (int it = 0; it < 4; it++) {
                    int row = crow + it * 32;
                    uint32_t s = base + op * 32768 + pan * 16384 + (uint32_t)row * 128 + swz16;
                    const __half* gp = Act + (size_t)(bm + row) * K2 + op * K +
                                       c * 128 + pan * 64 + cslot * 8;
                    cp16(s, gp);
                }
#pragma unroll
        for (int mat = 0; mat < 3; mat++)
#pragma unroll
            for (int pan = 0; pan < 2; pan++)
#pragma unroll
                for (int it = 0; it < 2; it++) {
                    int row = crow + it * 32;
                    uint32_t s = base + 65536 + mat * 16384 + pan * 8192 +
                                 (uint32_t)row * 128 + swz16;
                    const __half* gp = Bk + (size_t)mat * NK + (size_t)(bn + row) * K +
                                       c * 128 + pan * 64 + cslot * 8;
                    cp16(s, gp);
                }
        asm volatile("cp.async.commit_group;" ::: "memory");
    };

    issue(0);

    const uint32_t a_row = (uint32_t)(wm * 32 + lm) * 128;
    const uint32_t b_row = (uint32_t)(wn * 32 + lm) * 128;

    for (int c = 0; c < nch; c++) {
        asm volatile("cp.async.wait_group 0;" ::: "memory");
        __syncthreads();
        if (c + 1 < nch) issue(c + 1);
        const uint32_t cb = smb + (uint32_t)(c & 1) * KAR_BUF;

#pragma unroll
        for (int kk = 0; kk < 8; kk++) {
            const int pan = kk >> 2, ks = kk & 3;
            const uint32_t kslot = (uint32_t)(((ks * 2 + l16) ^ fx) << 4);
            uint32_t af[2][2][4];
            const uint32_t ab = cb + pan * 16384 + a_row + kslot;
            ldm_x4(af[0][0], ab);
            ldm_x4(af[0][1], ab + 16 * 128);
            ldm_x4(af[1][0], ab + 32768);
            ldm_x4(af[1][1], ab + 32768 + 16 * 128);
            uint32_t bf[3][4][2];
            const uint32_t bb = cb + 65536 + pan * 8192 + b_row + kslot;
#pragma unroll
            for (int mat = 0; mat < 3; mat++) {
                uint32_t r[4];
                ldm_x4(r, bb + mat * 16384);
                bf[mat][0][0] = r[0]; bf[mat][1][0] = r[1];
                bf[mat][0][1] = r[2]; bf[mat][1][1] = r[3];
                ldm_x4(r, bb + mat * 16384 + 16 * 128);
                bf[mat][2][0] = r[0]; bf[mat][3][0] = r[1];
                bf[mat][2][1] = r[2]; bf[mat][3][1] = r[3];
            }
            uint32_t as[2][4];
#pragma unroll
            for (int mt = 0; mt < 2; mt++)
#pragma unroll
                for (int i = 0; i < 4; i++)
                    as[mt][i] = hadd2u(af[0][mt][i], af[1][mt][i]);
#pragma unroll
            for (int mt = 0; mt < 2; mt++)
#pragma unroll
                for (int nt = 0; nt < 4; nt++) {
                    mma_f16(acc1[mt][nt], as[mt],    bf[0][nt]);
                    mma_f16(acc2[mt][nt], af[0][mt], bf[1][nt]);
                    mma_f16(acc3[mt][nt], af[1][mt], bf[2][nt]);
                }
        }
    }

#pragma unroll
    for (int mt = 0; mt < 2; mt++) {
        const int row0 = bm + wm * 32 + mt * 16 + g;
#pragma unroll
        for (int nt = 0; nt < 4; nt++) {
            const int col = bn + wn * 32 + nt * 8 + 2 * tq;
            const float br0 = br[col], br1 = br[col + 1];
            const float bi0 = bi[col], bi1 = bi[col + 1];
            const float* a1 = acc1[mt][nt];
            const float* a2 = acc2[mt][nt];
            const float* a3 = acc3[mt][nt];
            const float x0 = tanhf(a1[0] - a3[0] + br0);
            const float x1 = tanhf(a1[1] - a3[1] + br1);
            const float x2 = tanhf(a1[2] - a3[2] + br0);
            const float x3 = tanhf(a1[3] - a3[3] + br1);
            const float y0 = tanhf(a1[0] + a2[0] + bi0);
            const float y1 = tanhf(a1[1] + a2[1] + bi1);
            const float y2 = tanhf(a1[2] + a2[2] + bi0);
            const float y3 = tanhf(a1[3] + a2[3] + bi1);
            __half* o0 = Out + (size_t)row0 * (2 * N) + col;
            __half* o1 = Out + (size_t)(row0 + 8) * (2 * N) + col;
            *(__half2*)o0 = __floats2half2_rn(x0, x1);
            *(__half2*)o1 = __floats2half2_rn(x2, x3);
            *(__half2*)(o0 + N) = __floats2half2_rn(y0, y1);
            *(__half2*)(o1 + N) = __floats2half2_rn(y2, y3);
        }
    }
}

__device__ __forceinline__ void l2_body(
    char* sm, const __half* __restrict__ A, const __half* __restrict__ Bw,
    const float* __restrict__ bias, float* __restrict__ C, int K, int bnb, int bmb) {
    const uint32_t smb = smem_u32(sm);
    const int tid = threadIdx.x;
    const int wid = tid >> 5, lane = tid & 31;
    const int wm = wid >> 2, wn = wid & 3;
    const int g = lane >> 2, tq = lane & 3;
    const int lm = lane & 15, l16 = lane >> 4, fx = lane & 7;

    const int bm = bmb * 64;
    const int bn = bnb * 128;
    const int nch = K / 64;

    const int crow = tid >> 3;
    const int cslot = tid & 7;
    const uint32_t swz16 = (uint32_t)((cslot ^ (crow & 7)) << 4);
    const __half* Agb = A  + (size_t)(bm + crow) * K + cslot * 8;
    const __half* Bgb = Bw + (size_t)(bn + crow) * K + cslot * 8;

    float acc[2][4][4];
#pragma unroll
    for (int mt = 0; mt < 2; mt++)
#pragma unroll
        for (int nt = 0; nt < 4; nt++)
#pragma unroll
            for (int r = 0; r < 4; r++) acc[mt][nt][r] = 0.0f;

    auto issue = [&](int c) {
        const uint32_t base = smb + (uint32_t)(c & 1) * L2C;
#pragma unroll
        for (int it = 0; it < 2; it++)
            cp16(base + (uint32_t)(crow + it * 32) * 128 + swz16,
                 Agb + (size_t)it * 32 * K + c * 64);
#pragma unroll
        for (int it = 0; it < 4; it++)
            cp16(base + L2C_A + (uint32_t)(crow + it * 32) * 128 + swz16,
                 Bgb + (size_t)it * 32 * K + c * 64);
        asm volatile("cp.async.commit_group;" ::: "memory");
    };

    issue(0);

    const uint32_t a_row = (uint32_t)(wm * 32 + lm) * 128;
    const uint32_t b_row = (uint32_t)(wn * 32 + lm) * 128;

    for (int c = 0; c < nch; c++) {
        asm volatile("cp.async.wait_group 0;" ::: "memory");
        __syncthreads();
        if (c + 1 < nch) issue(c + 1);
        const uint32_t cb = smb + (uint32_t)(c & 1) * L2C;

#pragma unroll
        for (int kk = 0; kk < 4; kk++) {
            const uint32_t kslot = (uint32_t)(((kk * 2 + l16) ^ fx) << 4);
            uint32_t af[2][4];
            ldm_x4(af[0], cb + a_row + kslot);
            ldm_x4(af[1], cb + a_row + 16 * 128 + kslot);
            uint32_t bf[4][2];
#pragma unroll
            for (int p = 0; p < 2; p++) {
                uint32_t r[4];
                ldm_x4(r, cb + L2C_A + b_row + (uint32_t)(p * 16) * 128 + kslot);
                bf[2 * p][0] = r[0]; bf[2 * p + 1][0] = r[1];
                bf[2 * p][1] = r[2]; bf[2 * p + 1][1] = r[3];
            }
#pragma unroll
            for (int mt = 0; mt < 2; mt++)
#pragma unroll
                for (int nt = 0; nt < 4; nt++)
                    mma_f16(acc[mt][nt], af[mt], bf[nt]);
        }
    }

#pragma unroll
    for (int mt = 0; mt < 2; mt++) {
        const int row0 = bm + wm * 32 + mt * 16 + g;
#pragma unroll
        for (int nt = 0; nt < 4; nt++) {
            const int col = bn + wn * 32 + nt * 8 + 2 * tq;
            const float bv0 = bias[col], bv1 = bias[col + 1];
            const float v0 = tanhf(acc[mt][nt][0] + bv0);
            const float v1 = tanhf(acc[mt][nt][1] + bv1);
            const float v2 = tanhf(acc[mt][nt][2] + bv0);
            const float v3 = tanhf(acc[mt][nt][3] + bv1);
            const int t0 = row0 >> 6, b0 = row0 & 63;
            const int r1 = row0 + 8;
            const int t1 = r1 >> 6, b1 = r1 & 63;
            *(float2*)(C + (size_t)b0 * (STEPS * ACTION_DIM) + t0 * ACTION_DIM + col) =
                make_float2(v0, v1);
            *(float2*)(C + (size_t)b1 * (STEPS * ACTION_DIM) + t1 * ACTION_DIM + col) =
                make_float2(v2, v3);
        }
    }
}

// ---------------- fused 3-layer pipeline kernel (R11 structure) ----------------
__global__ __launch_bounds__(256, 1)
void mlp_fused(const __half* __restrict__ st, const __half* __restrict__ B0,
               const float* __restrict__ b0r, const float* __restrict__ b0i,
               __half* __restrict__ a1,
               const __half* __restrict__ B1,
               const float* __restrict__ b1r, const float* __restrict__ b1i,
               __half* __restrict__ a2,
               const __half* __restrict__ P2, const float* __restrict__ b2r,
               float* __restrict__ out) {
    extern __shared__ char sm[];
    const int b = blockIdx.x;
    if (b < 1024) {
        const int bn = b & 15, bm = b >> 4;
        kar_body(sm, st, B0, b0r, b0i, a1, 512, 1024, bn, bm);
        sig_cnt(&g_c0[bm]);
    } else if (b < 1536) {
        const int i = b - 1024;
        const int bn = i & 7, bm = i >> 3;
        wait_cnt(&g_c0[bm], 16);
        kar_body(sm, a1, B1, b1r, b1i, a2, 1024, 512, bn, bm);
        sig_cnt(&g_c1[bm]);
    } else {
        const int i = b - 1536;
        const int bn = i & 1, bm64 = i >> 1;
        wait_cnt(&g_c1[bm64 >> 1], 8);
        l2_body(sm, a2, P2, b2r, out, 1024, bn, bm64);
    }
}

// ---------------- launch ----------------
extern "C" void kernel_launch(void* const* d_in, const int* in_sizes, int n_in,
                              void* d_out, int out_size) {
    const float* z     = (const float*)d_in[0];
    const float* omega = (const float*)d_in[1];
    const float* bpar  = (const float*)d_in[2];
    const float* W0r = (const float*)d_in[3];
    const float* W0i = (const float*)d_in[4];
    const float* b0r = (const float*)d_in[5];
    const float* b0i = (const float*)d_in[6];
    const float* W1r = (const float*)d_in[7];
    const float* W1i = (const float*)d_in[8];
    const float* b1r = (const float*)d_in[9];
    const float* b1i = (const float*)d_in[10];
    const float* W2r = (const float*)d_in[11];
    const float* W2i = (const float*)d_in[12];
    const float* b2r = (const float*)d_in[13];

    float* out = (float*)d_out;                                 // (64, 128, 256)
    float* out_z1 = out + (size_t)BATCH * STEPS * ACTION_DIM;   // (64, 1024)

    __half *B0, *B1, *P2, *st, *a1, *a2;
    cudaGetSymbolAddress((void**)&B0, g_B0k);
    cudaGetSymbolAddress((void**)&B1, g_B1k);
    cudaGetSymbolAddress((void**)&P2, g_P2h);
    cudaGetSymbolAddress((void**)&st, g_states_h);
    cudaGetSymbolAddress((void**)&a1, g_act1_h);
    cudaGetSymbolAddress((void**)&a2, g_act2_h);

    constexpr int SM_FUSED = 2 * KAR_BUF;    // 229376
    cudaFuncSetAttribute(mlp_fused, cudaFuncAttributeMaxDynamicSharedMemorySize, SM_FUSED);

    // flat prep: one tile per CTA, hopf first (1344 CTAs, tiny smem)
    prep_flat<<<1344, 256>>>(z, omega, bpar,
                             W0r, W0i, W1r, W1i, W2r, W2i,
                             B0, B1, P2, st, out_z1);

    // fused L0 + L1 + L2 with per-row-block spin dependencies
    mlp_fused<<<1792, 256, SM_FUSED>>>(st, B0, b0r, b0i, a1,
                                       B1, b1r, b1i, a2,
                                       P2, b2r, out);
}

// round 17
// speedup vs baseline: 1.0900x; 1.0096x over previous
#include <cuda_runtime.h>
#include <cuda_fp16.h>
#include <math.h>
#include <cstdint>

#define DT 0.001f
#define STEPS 128
#define UNITS 512
#define BATCH 64
#define MROWS (STEPS * BATCH)   // 8192
#define ACTION_DIM 256

// ---------------- scratch ----------------
__device__ __half g_states_h[MROWS * 1024];   // [x(512) | y(512)]
__device__ __half g_act1_h[MROWS * 2048];     // [x(1024) | y(1024)]
__device__ __half g_act2_h[MROWS * 1024];     // [x(512) | y(512)]
__device__ __half g_B0k[3 * 1024 * 512];      // layer0 karatsuba B: [3][N=1024][K=512]
__device__ __half g_B1k[3 * 512 * 1024];      // layer1: [3][512][1024]
__device__ __half g_P2h[256 * 1024];          // layer2: [N=256][2K=1024]
__device__ int g_c0[64];                      // a1 row-block counters, target 16
__device__ int g_c1[64];                      // a2 row-block counters, target 8

__device__ __forceinline__ uint32_t smem_u32(const void* p) {
    uint32_t a;
    asm("{ .reg .u64 t; cvta.to.shared.u64 t, %1; cvt.u32.u64 %0, t; }" : "=r"(a) : "l"(p));
    return a;
}
__device__ __forceinline__ void cp16(uint32_t s, const void* g) {
    asm volatile("cp.async.cg.shared.global [%0], [%1], 16;" :: "r"(s), "l"(g));
}
__device__ __forceinline__ void ldm_x4(uint32_t* r, uint32_t addr) {
    asm volatile("ldmatrix.sync.aligned.m8n8.x4.shared.b16 {%0,%1,%2,%3}, [%4];"
                 : "=r"(r[0]), "=r"(r[1]), "=r"(r[2]), "=r"(r[3]) : "r"(addr));
}
__device__ __forceinline__ void mma_f16(float* c, const uint32_t* a, const uint32_t* b) {
    asm volatile(
        "mma.sync.aligned.m16n8k16.row.col.f32.f16.f16.f32 "
        "{%0,%1,%2,%3}, {%4,%5,%6,%7}, {%8,%9}, {%0,%1,%2,%3};"
        : "+f"(c[0]), "+f"(c[1]), "+f"(c[2]), "+f"(c[3])
        : "r"(a[0]), "r"(a[1]), "r"(a[2]), "r"(a[3]), "r"(b[0]), "r"(b[1]));
}
__device__ __forceinline__ uint32_t hadd2u(uint32_t a, uint32_t b) {
    __half2 r = __hadd2(*(__half2*)&a, *(__half2*)&b);
    return *(uint32_t*)&r;
}
// cross-CTA dependency primitives
__device__ __forceinline__ void wait_cnt(int* p, int target) {
    if (threadIdx.x == 0) {
        int v;
        for (;;) {
            asm volatile("ld.acquire.gpu.global.s32 %0, [%1];" : "=r"(v) : "l"(p));
            if (v >= target) break;
            __nanosleep(128);
        }
    }
    __syncthreads();
}
__device__ __forceinline__ void sig_cnt(int* p) {
    __threadfence();
    __syncthreads();
    if (threadIdx.x == 0) atomicAdd(p, 1);
}

// ---------------- prep: single-wave grid (960 CTAs) ----------------
__device__ __forceinline__ void pack_kar_tile(
    const float* __restrict__ Wr, const float* __restrict__ Wi,
    __half* __restrict__ Bk, int K, int N, int k0, int n0,
    float (*tr)[33], float (*ti)[33], int tx, int ty0) {
#pragma unroll
    for (int i = 0; i < 4; i++) {
        int ty = ty0 + i * 8;
        tr[ty][tx] = Wr[(size_t)(k0 + ty) * N + n0 + tx];
        ti[ty][tx] = Wi[(size_t)(k0 + ty) * N + n0 + tx];
    }
    __syncthreads();
    const size_t NK = (size_t)N * K;
#pragma unroll
    for (int i = 0; i < 4; i++) {
        int ty = ty0 + i * 8;
        float wr = tr[tx][ty], wi = ti[tx][ty];
        size_t o = (size_t)(n0 + ty) * K + k0 + tx;
        Bk[o] = __float2half_rn(wr);
        Bk[NK + o] = __float2half_rn(wi - wr);
        Bk[2 * NK + o] = __float2half_rn(wr + wi);
    }
}
// two independent tiles, one shared barrier (loads of both overlap)
__device__ __forceinline__ void pack_kar_tile2(
    const float* __restrict__ Wr, const float* __restrict__ Wi,
    __half* __restrict__ Bk, int K, int N,
    int k0a, int n0a, int k0b, int n0b,
    float (*t1)[33], float (*t2)[33], float (*t3)[33], float (*t4)[33],
    int tx, int ty0) {
#pragma unroll
    for (int i = 0; i < 4; i++) {
        int ty = ty0 + i * 8;
        t1[ty][tx] = Wr[(size_t)(k0a + ty) * N + n0a + tx];
        t2[ty][tx] = Wi[(size_t)(k0a + ty) * N + n0a + tx];
        t3[ty][tx] = Wr[(size_t)(k0b + ty) * N + n0b + tx];
        t4[ty][tx] = Wi[(size_t)(k0b + ty) * N + n0b + tx];
    }
    __syncthreads();
    const size_t NK = (size_t)N * K;
#pragma unroll
    for (int i = 0; i < 4; i++) {
        int ty = ty0 + i * 8;
        float wr = t1[tx][ty], wi = t2[tx][ty];
        size_t o = (size_t)(n0a + ty) * K + k0a + tx;
        Bk[o] = __float2half_rn(wr);
        Bk[NK + o] = __float2half_rn(wi - wr);
        Bk[2 * NK + o] = __float2half_rn(wr + wi);
        wr = t3[tx][ty]; wi = t4[tx][ty];
        o = (size_t)(n0b + ty) * K + k0b + tx;
        Bk[o] = __float2half_rn(wr);
        Bk[NK + o] = __float2half_rn(wi - wr);
        Bk[2 * NK + o] = __float2half_rn(wr + wi);
    }
}
__device__ __forceinline__ void pack_half_tile2(
    const float* __restrict__ Wr, const float* __restrict__ Wi,
    __half* __restrict__ PT, int K, int N,
    int k0a, int n0a, int k0b, int n0b,
    float (*t1)[33], float (*t2)[33], int tx, int ty0) {
#pragma unroll
    for (int i = 0; i < 4; i++) {
        int ty = ty0 + i * 8;
        int ka = k0a + ty, kb = k0b + ty;
        t1[ty][tx] = (ka < K) ? Wr[(size_t)ka * N + n0a + tx]
                              : -Wi[(size_t)(ka - K) * N + n0a + tx];
        t2[ty][tx] = (kb < K) ? Wr[(size_t)kb * N + n0b + tx]
                              : -Wi[(size_t)(kb - K) * N + n0b + tx];
    }
    __syncthreads();
#pragma unroll
    for (int i = 0; i < 4; i++) {
        int ty = ty0 + i * 8;
        PT[(size_t)(n0a + ty) * (2 * K) + k0a + tx] = __float2half_rn(t1[tx][ty]);
        PT[(size_t)(n0b + ty) * (2 * K) + k0b + tx] = __float2half_rn(t2[tx][ty]);
    }
}
// hopf: two adjacent units per thread, half2/float2 stores, peeled t=0
__device__ __forceinline__ void hopf1d(
    int blk, const float* __restrict__ z0, const float* __restrict__ omega,
    const float* __restrict__ bpar, __half* __restrict__ states,
    float* __restrict__ out_z1) {
    int tid = blk * 256 + threadIdx.x;              // 0..16383
    int bi = tid >> 8;
    int j = tid & 255;
    int i0 = 2 * j;
    const float om = omega[bi];
    float2 xz = *(const float2*)(z0 + bi * 1024 + i0);
    float2 yz = *(const float2*)(z0 + bi * 1024 + UNITS + i0);
    float x0 = xz.x, x1 = xz.y, y0 = yz.x, y1 = yz.y;
    const float w0 = om * (float)(i0 + 1), w1 = om * (float)(i0 + 2);
    const float b0 = bpar[bi * UNITS + i0], b1 = bpar[bi * UNITS + i0 + 1];

    // t = 0 (peeled: also writes z1 to output)
    {
        float g0 = b0 - (x0 * x0 + y0 * y0), g1 = b1 - (x1 * x1 + y1 * y1);
        float dx0 = g0 * x0 - w0 * y0, dy0 = g0 * y0 + w0 * x0;
        float dx1 = g1 * x1 - w1 * y1, dy1 = g1 * y1 + w1 * x1;
        x0 += DT * dx0; y0 += DT * dy0;
        x1 += DT * dx1; y1 += DT * dy1;
        __half* row = states + ((size_t)bi) * 1024;
        *(__half2*)(row + i0) = __floats2half2_rn(x0, x1);
        *(__half2*)(row + UNITS + i0) = __floats2half2_rn(y0, y1);
        *(float2*)(out_z1 + bi * 1024 + i0) = make_float2(x0, x1);
        *(float2*)(out_z1 + bi * 1024 + UNITS + i0) = make_float2(y0, y1);
    }
#pragma unroll 4
    for (int t = 1; t < STEPS; t++) {
        float g0 = b0 - (x0 * x0 + y0 * y0), g1 = b1 - (x1 * x1 + y1 * y1);
        float dx0 = g0 * x0 - w0 * y0, dy0 = g0 * y0 + w0 * x0;
        float dx1 = g1 * x1 - w1 * y1, dy1 = g1 * y1 + w1 * x1;
        x0 += DT * dx0; y0 += DT * dy0;
        x1 += DT * dx1; y1 += DT * dy1;
        __half* row = states + ((size_t)(t * BATCH + bi)) * 1024;
        *(__half2*)(row + i0) = __floats2half2_rn(x0, x1);
        *(__half2*)(row + UNITS + i0) = __floats2half2_rn(y0, y1);
    }
}
// 960 CTAs (single wave):
// [0,64) hopf; [64,576) B0 1-tile; [576,832) B1 2-tiles; [832,960) P2 2-tiles (+reset)
__global__ __launch_bounds__(256)
void prep_flat(const float* z, const float* omega, const float* bpar,
               const float* W0r, const float* W0i,
               const float* W1r, const float* W1i,
               const float* W2r, const float* W2i,
               __half* B0, __half* B1, __half* P2,
               __half* states, float* out_z1) {
    __shared__ float t1[32][33], t2[32][33], t3[32][33], t4[32][33];
    const int b = blockIdx.x;
    const int tid = threadIdx.x;
    const int tx = tid & 31, ty0 = tid >> 5;
    if (b < 64) {
        hopf1d(b, z, omega, bpar, states, out_z1);
    } else if (b < 576) {
        const int tt = b - 64;                 // 512 tiles: K=512(16) x N=1024(32)
        pack_kar_tile(W0r, W0i, B0, 512, 1024, (tt & 15) * 32, (tt >> 4) * 32,
                      t1, t2, tx, ty0);
    } else if (b < 832) {
        const int ta = b - 576;                // B1: 512 tiles, 2 per CTA
        const int tb = ta + 256;               // grid 32(K) x 16(N)
        pack_kar_tile2(W1r, W1i, B1, 1024, 512,
                       (ta & 31) * 32, (ta >> 5) * 32,
                       (tb & 31) * 32, (tb >> 5) * 32,
                       t1, t2, t3, t4, tx, ty0);
    } else {
        if (b == 832 && tid < 64) { g_c0[tid] = 0; g_c1[tid] = 0; }
        const int ta = b - 832;                // P2: 256 tiles, 2 per CTA
        const int tb = ta + 128;               // grid 32(2K) x 8(N)
        pack_half_tile2(W2r, W2i, P2, 512, 256,
                        (ta & 31) * 32, (ta >> 5) * 32,
                        (tb & 31) * 32, (tb >> 5) * 32,
                        t1, t2, tx, ty0);
    }
}

// ---------------- fused GEMM pipeline bodies (R11, tanhf) ----------------
#define KAR_BUF 114688   // per-buffer smem: Ax 32K + Ay 32K + B 48K
#define L2C_A  (64 * 128)
#define L2C    (L2C_A + 128 * 128)

__device__ __forceinline__ void kar_body(
    char* sm, const __half* __restrict__ Act, const __half* __restrict__ Bk,
    const float* __restrict__ br, const float* __restrict__ bi,
    __half* __restrict__ Out, int K, int N, int bnb, int bmb) {
    const uint32_t smb = smem_u32(sm);
    const int tid = threadIdx.x;
    const int wid = tid >> 5, lane = tid & 31;
    const int wm = wid >> 1, wn = wid & 1;
    const int g = lane >> 2, tq = lane & 3;
    const int lm = lane & 15, l16 = lane >> 4, fx = lane & 7;

    const int bm = bmb * 128;
    const int bn = bnb * 64;
    const int nch = K / 128;
    const int K2 = 2 * K;
    const size_t NK = (size_t)N * K;

    const int crow = tid >> 3;
    const int cslot = tid & 7;
    const uint32_t swz16 = (uint32_t)((cslot ^ (crow & 7)) << 4);

    float acc1[2][4][4], acc2[2][4][4], acc3[2][4][4];
#pragma unroll
    for (int mt = 0; mt < 2; mt++)
#pragma unroll
        for (int nt = 0; nt < 4; nt++)
#pragma unroll
            for (int r = 0; r < 4; r++) {
                acc1[mt][nt][r] = 0.0f; acc2[mt][nt][r] = 0.0f; acc3[mt][nt][r] = 0.0f;
            }

    auto issue = [&](int c) {
        const uint32_t base = smb + (uint32_t)(c & 1) * KAR_BUF;
#pragma unroll
        for (int op = 0; op < 2; op++)
#pragma unroll
            for (int pan = 0; pan < 2; pan++)
#pragma unroll
                for (int it = 0; it < 4; it++) {
                    int row = crow + it * 32;
                    uint32_t s = base + op * 32768 + pan * 16384 + (uint32_t)row * 128 + swz16;
                    const __half* gp = Act + (size_t)(bm + row) * K2 + op * K +
                                       c * 128 + pan * 64 + cslot * 8;
                    cp16(s, gp);
                }
#pragma unroll
        for (int mat = 0; mat < 3; mat++)
#pragma unroll
            for (int pan = 0; pan < 2; pan++)
#pragma unroll
                for (int it = 0; it < 2; it++) {
                    int row = crow + it * 32;
                    uint32_t s = base + 65536 + mat * 16384 + pan * 8192 +
                                 (uint32_t)row * 128 + swz16;
                    const __half* gp = Bk + (size_t)mat * NK + (size_t)(bn + row) * K +
                                       c * 128 + pan * 64 + cslot * 8;
                    cp16(s, gp);
                }
        asm volatile("cp.async.commit_group;" ::: "memory");
    };

    issue(0);

    const uint32_t a_row = (uint32_t)(wm * 32 + lm) * 128;
    const uint32_t b_row = (uint32_t)(wn * 32 + lm) * 128;

    for (int c = 0; c < nch; c++) {
        asm volatile("cp.async.wait_group 0;" ::: "memory");
        __syncthreads();
        if (c + 1 < nch) issue(c + 1);
        const uint32_t cb = smb + (uint32_t)(c & 1) * KAR_BUF;

#pragma unroll
        for (int kk = 0; kk < 8; kk++) {
            const int pan = kk >> 2, ks = kk & 3;
            const uint32_t kslot = (uint32_t)(((ks * 2 + l16) ^ fx) << 4);
            uint32_t af[2][2][4];
            const uint32_t ab = cb + pan * 16384 + a_row + kslot;
            ldm_x4(af[0][0], ab);
            ldm_x4(af[0][1], ab + 16 * 128);
            ldm_x4(af[1][0], ab + 32768);
            ldm_x4(af[1][1], ab + 32768 + 16 * 128);
            uint32_t bf[3][4][2];
            const uint32_t bb = cb + 65536 + pan * 8192 + b_row + kslot;
#pragma unroll
            for (int mat = 0; mat < 3; mat++) {
                uint32_t r[4];
                ldm_x4(r, bb + mat * 16384);
                bf[mat][0][0] = r[0]; bf[mat][1][0] = r[1];
                bf[mat][0][1] = r[2]; bf[mat][1][1] = r[3];
                ldm_x4(r, bb + mat * 16384 + 16 * 128);
                bf[mat][2][0] = r[0]; bf[mat][3][0] = r[1];
                bf[mat][2][1] = r[2]; bf[mat][3][1] = r[3];
            }
            uint32_t as[2][4];
#pragma unroll
            for (int mt = 0; mt < 2; mt++)
#pragma unroll
                for (int i = 0; i < 4; i++)
                    as[mt][i] = hadd2u(af[0][mt][i], af[1][mt][i]);
#pragma unroll
            for (int mt = 0; mt < 2; mt++)
#pragma unroll
                for (int nt = 0; nt < 4; nt++) {
                    mma_f16(acc1[mt][nt], as[mt],    bf[0][nt]);
                    mma_f16(acc2[mt][nt], af[0][mt], bf[1][nt]);
                    mma_f16(acc3[mt][nt], af[1][mt], bf[2][nt]);
                }
        }
    }

#pragma unroll
    for (int mt = 0; mt < 2; mt++) {
        const int row0 = bm + wm * 32 + mt * 16 + g;
#pragma unroll
        for (int nt = 0; nt < 4; nt++) {
            const int col = bn + wn * 32 + nt * 8 + 2 * tq;
            const float br0 = br[col], br1 = br[col + 1];
            const float bi0 = bi[col], bi1 = bi[col + 1];
            const float* a1 = acc1[mt][nt];
            const float* a2 = acc2[mt][nt];
            const float* a3 = acc3[mt][nt];
            const float x0 = tanhf(a1[0] - a3[0] + br0);
            const float x1 = tanhf(a1[1] - a3[1] + br1);
            const float x2 = tanhf(a1[2] - a3[2] + br0);
            const float x3 = tanhf(a1[3] - a3[3] + br1);
            const float y0 = tanhf(a1[0] + a2[0] + bi0);
            const float y1 = tanhf(a1[1] + a2[1] + bi1);
            const float y2 = tanhf(a1[2] + a2[2] + bi0);
            const float y3 = tanhf(a1[3] + a2[3] + bi1);
            __half* o0 = Out + (size_t)row0 * (2 * N) + col;
            __half* o1 = Out + (size_t)(row0 + 8) * (2 * N) + col;
            *(__half2*)o0 = __floats2half2_rn(x0, x1);
            *(__half2*)o1 = __floats2half2_rn(x2, x3);
            *(__half2*)(o0 + N) = __floats2half2_rn(y0, y1);
            *(__half2*)(o1 + N) = __floats2half2_rn(y2, y3);
        }
    }
}

__device__ __forceinline__ void l2_body(
    char* sm, const __half* __restrict__ A, const __half* __restrict__ Bw,
    const float* __restrict__ bias, float* __restrict__ C, int K, int bnb, int bmb) {
    const uint32_t smb = smem_u32(sm);
    const int tid = threadIdx.x;
    const int wid = tid >> 5, lane = tid & 31;
    const int wm = wid >> 2, wn = wid & 3;
    const int g = lane >> 2, tq = lane & 3;
    const int lm = lane & 15, l16 = lane >> 4, fx = lane & 7;

    const int bm = bmb * 64;
    const int bn = bnb * 128;
    const int nch = K / 64;

    const int crow = tid >> 3;
    const int cslot = tid & 7;
    const uint32_t swz16 = (uint32_t)((cslot ^ (crow & 7)) << 4);
    const __half* Agb = A  + (size_t)(bm + crow) * K + cslot * 8;
    const __half* Bgb = Bw + (size_t)(bn + crow) * K + cslot * 8;

    float acc[2][4][4];
#pragma unroll
    for (int mt = 0; mt < 2; mt++)
#pragma unroll
        for (int nt = 0; nt < 4; nt++)
#pragma unroll
            for (int r = 0; r < 4; r++) acc[mt][nt][r] = 0.0f;

    auto issue = [&](int c) {
        const uint32_t base = smb + (uint32_t)(c & 1) * L2C;
#pragma unroll
        for (int it = 0; it < 2; it++)
            cp16(base + (uint32_t)(crow + it * 32) * 128 + swz16,
                 Agb + (size_t)it * 32 * K + c * 64);
#pragma unroll
        for (int it = 0; it < 4; it++)
            cp16(base + L2C_A + (uint32_t)(crow + it * 32) * 128 + swz16,
                 Bgb + (size_t)it * 32 * K + c * 64);
        asm volatile("cp.async.commit_group;" ::: "memory");
    };

    issue(0);

    const uint32_t a_row = (uint32_t)(wm * 32 + lm) * 128;
    const uint32_t b_row = (uint32_t)(wn * 32 + lm) * 128;

    for (int c = 0; c < nch; c++) {
        asm volatile("cp.async.wait_group 0;" ::: "memory");
        __syncthreads();
        if (c + 1 < nch) issue(c + 1);
        const uint32_t cb = smb + (uint32_t)(c & 1) * L2C;

#pragma unroll
        for (int kk = 0; kk < 4; kk++) {
            const uint32_t kslot = (uint32_t)(((kk * 2 + l16) ^ fx) << 4);
            uint32_t af[2][4];
            ldm_x4(af[0], cb + a_row + kslot);
            ldm_x4(af[1], cb + a_row + 16 * 128 + kslot);
            uint32_t bf[4][2];
#pragma unroll
            for (int p = 0; p < 2; p++) {
                uint32_t r[4];
                ldm_x4(r, cb + L2C_A + b_row + (uint32_t)(p * 16) * 128 + kslot);
                bf[2 * p][0] = r[0]; bf[2 * p + 1][0] = r[1];
                bf[2 * p][1] = r[2]; bf[2 * p + 1][1] = r[3];
            }
#pragma unroll
            for (int mt = 0; mt < 2; mt++)
#pragma unroll
                for (int nt = 0; nt < 4; nt++)
                    mma_f16(acc[mt][nt], af[mt], bf[nt]);
        }
    }

#pragma unroll
    for (int mt = 0; mt < 2; mt++) {
        const int row0 = bm + wm * 32 + mt * 16 + g;
#pragma unroll
        for (int nt = 0; nt < 4; nt++) {
            const int col = bn + wn * 32 + nt * 8 + 2 * tq;
            const float bv0 = bias[col], bv1 = bias[col + 1];
            const float v0 = tanhf(acc[mt][nt][0] + bv0);
            const float v1 = tanhf(acc[mt][nt][1] + bv1);
            const float v2 = tanhf(acc[mt][nt][2] + bv0);
            const float v3 = tanhf(acc[mt][nt][3] + bv1);
            const int t0 = row0 >> 6, b0 = row0 & 63;
            const int r1 = row0 + 8;
            const int t1 = r1 >> 6, b1 = r1 & 63;
            *(float2*)(C + (size_t)b0 * (STEPS * ACTION_DIM) + t0 * ACTION_DIM + col) =
                make_float2(v0, v1);
            *(float2*)(C + (size_t)b1 * (STEPS * ACTION_DIM) + t1 * ACTION_DIM + col) =
                make_float2(v2, v3);
        }
    }
}

// ---------------- fused 3-layer pipeline kernel (R11 structure) ----------------
__global__ __launch_bounds__(256, 1)
void mlp_fused(const __half* __restrict__ st, const __half* __restrict__ B0,
               const float* __restrict__ b0r, const float* __restrict__ b0i,
               __half* __restrict__ a1,
               const __half* __restrict__ B1,
               const float* __restrict__ b1r, const float* __restrict__ b1i,
               __half* __restrict__ a2,
               const __half* __restrict__ P2, const float* __restrict__ b2r,
               float* __restrict__ out) {
    extern __shared__ char sm[];
    const int b = blockIdx.x;
    if (b < 1024) {
        const int bn = b & 15, bm = b >> 4;
        kar_body(sm, st, B0, b0r, b0i, a1, 512, 1024, bn, bm);
        sig_cnt(&g_c0[bm]);
    } else if (b < 1536) {
        const int i = b - 1024;
        const int bn = i & 7, bm = i >> 3;
        wait_cnt(&g_c0[bm], 16);
        kar_body(sm, a1, B1, b1r, b1i, a2, 1024, 512, bn, bm);
        sig_cnt(&g_c1[bm]);
    } else {
        const int i = b - 1536;
        const int bn = i & 1, bm64 = i >> 1;
        wait_cnt(&g_c1[bm64 >> 1], 8);
        l2_body(sm, a2, P2, b2r, out, 1024, bn, bm64);
    }
}

// ---------------- launch ----------------
extern "C" void kernel_launch(void* const* d_in, const int* in_sizes, int n_in,
                              void* d_out, int out_size) {
    const float* z     = (const float*)d_in[0];
    const float* omega = (const float*)d_in[1];
    const float* bpar  = (const float*)d_in[2];
    const float* W0r = (const float*)d_in[3];
    const float* W0i = (const float*)d_in[4];
    const float* b0r = (const float*)d_in[5];
    const float* b0i = (const float*)d_in[6];
    const float* W1r = (const float*)d_in[7];
    const float* W1i = (const float*)d_in[8];
    const float* b1r = (const float*)d_in[9];
    const float* b1i = (const float*)d_in[10];
    const float* W2r = (const float*)d_in[11];
    const float* W2i = (const float*)d_in[12];
    const float* b2r = (const float*)d_in[13];

    float* out = (float*)d_out;                                 // (64, 128, 256)
    float* out_z1 = out + (size_t)BATCH * STEPS * ACTION_DIM;   // (64, 1024)

    __half *B0, *B1, *P2, *st, *a1, *a2;
    cudaGetSymbolAddress((void**)&B0, g_B0k);
    cudaGetSymbolAddress((void**)&B1, g_B1k);
    cudaGetSymbolAddress((void**)&P2, g_P2h);
    cudaGetSymbolAddress((void**)&st, g_states_h);
    cudaGetSymbolAddress((void**)&a1, g_act1_h);
    cudaGetSymbolAddress((void**)&a2, g_act2_h);

    constexpr int SM_FUSED = 2 * KAR_BUF;    // 229376
    cudaFuncSetAttribute(mlp_fused, cudaFuncAttributeMaxDynamicSharedMemorySize, SM_FUSED);

    // single-wave prep: hopf + packs + counter reset (960 CTAs, tiny smem)
    prep_flat<<<960, 256>>>(z, omega, bpar,
                            W0r, W0i, W1r, W1i, W2r, W2i,
                            B0, B1, P2, st, out_z1);

    // fused L0 + L1 + L2 with per-row-block spin dependencies
    mlp_fused<<<1792, 256, SM_FUSED>>>(st, B0, b0r, b0i, a1,
                                       B1, b1r, b1i, a2,
                                       P2, b2r, out);
}